// round 11
// baseline (speedup 1.0000x reference)
#include <cuda_runtime.h>
#include <cuda_fp16.h>
#include <cstdint>

// ---------------------------------------------------------------------------
// GNNEncoder: 2x (EdgeConv -> BatchNorm) + mean/max pooling
//
// Algebra: concat[x_i, x_j-x_i] @ Wa = x_i@(Wtop-Wbot) + x_j@Wbot
//   => per-node A[i], B[j]; per-edge layer-1 is A[dst]+B[src]
// BatchNorm folded into next node GEMM / pooling. Edges counting-sorted by
// dst => run-dedup atomicMax epilogue.
// R11: per-tile fixed costs dominate (profile: tensor 3%, issue 16%) =>
//      TILE_E 256 (half the tiles, half the barriers/overheads), simplified
//      unpipelined phases, STS.128 A-tile stores, 32-edge dedup runs.
//      bf16 3-term split (exact hi + truncated lo), fp32 accum.
// ---------------------------------------------------------------------------

#define HC 64
#define NMAX 50000
#define EMAX 1600000
#define NEG_INF_BITS ((int)0xFF800000u)

typedef unsigned long long u64;

#define FMA2(d, a, b, c) \
    asm("fma.rn.f32x2 %0, %1, %2, %3;" : "=l"(d) : "l"(a), "l"(b), "l"(c))
#define PACK2(d, v) \
    asm("mov.b64 %0, {%1, %1};" : "=l"(d) : "r"(v))
#define UNPACK2(lo, hi, v) \
    asm("mov.b64 {%0, %1}, %2;" : "=r"(lo), "=r"(hi) : "l"(v))

// fp32-accumulator bf16 HMMA
#define MMAB16(c, a0, a1, a2, a3, b0, b1)                                    \
    asm volatile(                                                            \
        "mma.sync.aligned.m16n8k16.row.col.f32.bf16.bf16.f32 "               \
        "{%0,%1,%2,%3}, {%4,%5,%6,%7}, {%8,%9}, {%0,%1,%2,%3};"              \
        : "+f"((c)[0]), "+f"((c)[1]), "+f"((c)[2]), "+f"((c)[3])             \
        : "r"(a0), "r"(a1), "r"(a2), "r"(a3), "r"(b0), "r"(b1))

__device__ int   g_cnt[NMAX];
__device__ int   g_chunk[256];
__device__ int   g_src[EMAX];
__device__ int   g_dst[EMAX];
__device__ float g_A[NMAX * HC];
__device__ float g_B[NMAX * HC];
__device__ int   g_raw1[NMAX * HC];   // float bits, atomicMax as signed int
__device__ int   g_raw2[NMAX * HC];
__device__ float g_part[128 * 2 * HC];
__device__ float g_scale[2 * HC];
__device__ float g_shift[2 * HC];

// ---------------------------- small utilities ------------------------------

__global__ void k_init_raw(int layer, int n, int ncnt) {
    int* raw = layer ? g_raw2 : g_raw1;
    for (int i = blockIdx.x * blockDim.x + threadIdx.x; i < n;
         i += gridDim.x * blockDim.x) {
        raw[i] = NEG_INF_BITS;
        if (i < ncnt) g_cnt[i] = 0;
    }
}

__global__ void k_hist(const int* __restrict__ dst, int E) {
    for (int e = blockIdx.x * blockDim.x + threadIdx.x; e < E;
         e += gridDim.x * blockDim.x)
        atomicAdd(&g_cnt[dst[e]], 1);
}

__global__ void k_scan1(int n) {  // blockDim = 1024
    __shared__ int s[1024];
    int i = blockIdx.x * 1024 + threadIdx.x;
    int v = (i < n) ? g_cnt[i] : 0;
    s[threadIdx.x] = v;
    __syncthreads();
    for (int off = 1; off < 1024; off <<= 1) {
        int t = 0;
        if (threadIdx.x >= off) t = s[threadIdx.x - off];
        __syncthreads();
        s[threadIdx.x] += t;
        __syncthreads();
    }
    if (i < n) g_cnt[i] = s[threadIdx.x] - v;   // exclusive within chunk
    if (threadIdx.x == 1023) g_chunk[blockIdx.x] = s[1023];
}

__global__ void k_scan2(int nch) {  // blockDim = 64, nch <= 64
    __shared__ int s[64];
    int i = threadIdx.x;
    int v = (i < nch) ? g_chunk[i] : 0;
    s[i] = v;
    __syncthreads();
    for (int off = 1; off < 64; off <<= 1) {
        int t = (i >= off) ? s[i - off] : 0;
        __syncthreads();
        s[i] += t;
        __syncthreads();
    }
    if (i < nch) g_chunk[i] = s[i] - v;   // exclusive
}

__global__ void k_scan3(int n) {
    int i = blockIdx.x * blockDim.x + threadIdx.x;
    if (i < n) g_cnt[i] += g_chunk[i >> 10];
}

__global__ void k_scatter(const int* __restrict__ src,
                          const int* __restrict__ dst, int E) {
    for (int e = blockIdx.x * blockDim.x + threadIdx.x; e < E;
         e += gridDim.x * blockDim.x) {
        int d = dst[e];
        int p = atomicAdd(&g_cnt[d], 1);
        g_src[p] = src[e];
        g_dst[p] = d;
    }
}

// ------------------------- per-node linear (A, B) ---------------------------

__global__ __launch_bounds__(256) void k_nodelin(
    const float* __restrict__ xin, int use_raw,
    const float* __restrict__ Wa,  // [128,64] row-major
    const float* __restrict__ ba, int n) {
    __shared__ float Ws[128 * 64];
    __shared__ float xs[32 * 65];
    int tid = threadIdx.x;
    for (int i = tid; i < 128 * 64; i += 256) Ws[i] = Wa[i];

    int row0 = blockIdx.x * 32;
    for (int i = tid; i < 32 * 64; i += 256) {
        int r = i >> 6, k = i & 63;
        int row = row0 + r;
        float v = 0.f;
        if (row < n) {
            if (use_raw)
                v = __int_as_float(g_raw1[row * 64 + k]) * g_scale[k] + g_shift[k];
            else
                v = xin[row * 64 + k];
        }
        xs[r * 65 + k] = v;
    }
    __syncthreads();

    int r = tid & 31, cg = tid >> 5;
    int c0 = cg * 8;
    u64 a2[4], b2[4];
#pragma unroll
    for (int j = 0; j < 4; j++) { a2[j] = 0ull; b2[j] = 0ull; }

#pragma unroll 8
    for (int k = 0; k < 64; k++) {
        float xv = xs[r * 65 + k];
        u64 xp;
        PACK2(xp, __float_as_uint(xv));
        ulonglong2 t0 = *(const ulonglong2*)&Ws[k * 64 + c0];
        ulonglong2 t1 = *(const ulonglong2*)&Ws[k * 64 + c0 + 4];
        ulonglong2 q0 = *(const ulonglong2*)&Ws[(64 + k) * 64 + c0];
        ulonglong2 q1 = *(const ulonglong2*)&Ws[(64 + k) * 64 + c0 + 4];
        FMA2(a2[0], xp, t0.x, a2[0]);
        FMA2(a2[1], xp, t0.y, a2[1]);
        FMA2(a2[2], xp, t1.x, a2[2]);
        FMA2(a2[3], xp, t1.y, a2[3]);
        FMA2(b2[0], xp, q0.x, b2[0]);
        FMA2(b2[1], xp, q0.y, b2[1]);
        FMA2(b2[2], xp, q1.x, b2[2]);
        FMA2(b2[3], xp, q1.y, b2[3]);
    }
    int row = row0 + r;
    if (row < n) {
        float a[8], b[8];
#pragma unroll
        for (int j = 0; j < 4; j++) {
            unsigned int lo, hi;
            UNPACK2(lo, hi, a2[j]);
            a[2 * j] = __uint_as_float(lo);
            a[2 * j + 1] = __uint_as_float(hi);
            UNPACK2(lo, hi, b2[j]);
            b[2 * j] = __uint_as_float(lo);
            b[2 * j + 1] = __uint_as_float(hi);
        }
#pragma unroll
        for (int j = 0; j < 8; j++) {
            float bb = ba[c0 + j];
            g_A[row * 64 + c0 + j] = a[j] - b[j] + bb;
            g_B[row * 64 + c0 + j] = b[j];
        }
    }
}

// -------------- edge kernel (256-edge tiles, bf16 3-term split) -------------
// k-order permuted identically in A and W tiles (dot products invariant):
// orig k-pair word w stored at pos = (w&3)*8 + (w>>2); MMA thread fragments
// are then contiguous (LDS.64) and gather stores are uint4 (STS.128).
// 16 warps: warp (eg 0..7, nh 0..1) = 32 edges x 32 cols, 2 MMA patches.

#define TILE_E 256
#define AROW 36                             // u32 stride per edge row (16B-align)
// dynamic smem (bytes)
#define SMO_DS   0                          // int [256]
#define SMO_SS   1024                       // int [256]
#define SMO_AH   2048                       // [256][36] u32 = 36864 B
#define SMO_AL   38912                      // 36864 B
#define SMO_STG  75776                      // [64][264] f32 = 67584 B
#define SMO_WTH  75776                      // init-only alias, [64][36] u32
#define SMO_WTL  84992                      // init-only alias
#define SM_EDGE_TOTAL 143360

// bf16 split: hi = top 16 bits (truncate), lo = (x - hi) truncated again.
__device__ __forceinline__ uint32_t bfpack(float x0, float x1,
                                           float& l0, float& l1) {
    uint32_t u0 = __float_as_uint(x0), u1 = __float_as_uint(x1);
    l0 = x0 - __uint_as_float(u0 & 0xFFFF0000u);
    l1 = x1 - __uint_as_float(u1 & 0xFFFF0000u);
    return __byte_perm(u0, u1, 0x7632);
}
__device__ __forceinline__ uint32_t bfpack2(float l0, float l1) {
    return __byte_perm(__float_as_uint(l0), __float_as_uint(l1), 0x7632);
}

__global__ __launch_bounds__(512, 1) void k_edge_mma(
    const float* __restrict__ Wb,   // [64k][64n]
    const float* __restrict__ bb,   // [64]
    const int* __restrict__ psrc, const int* __restrict__ pdst, int use_p,
    int tile_begin, int tile_end, int E, int layer) {
    extern __shared__ char sm[];
    int* ds = (int*)(sm + SMO_DS);
    int* ss = (int*)(sm + SMO_SS);
    uint32_t* AH = (uint32_t*)(sm + SMO_AH);
    uint32_t* AL = (uint32_t*)(sm + SMO_AL);
    float* STG = (float*)(sm + SMO_STG);
    uint32_t* WTH = (uint32_t*)(sm + SMO_WTH);
    uint32_t* WTL = (uint32_t*)(sm + SMO_WTL);

    const int* SRC = use_p ? psrc : g_src;
    const int* DST = use_p ? pdst : g_dst;

    int* out = layer ? g_raw2 : g_raw1;
    int tid = threadIdx.x;
    int wid = tid >> 5, lid = tid & 31;
    int gid = lid >> 2, tig = lid & 3;
    int eg = wid & 7, nh = wid >> 3;

    // ---- W split -> SMEM in permuted-k fragment layout ----
    for (int i = tid; i < 64 * 32; i += 512) {
        int n = i >> 5, wp = i & 31;           // orig k-pair index wp
        float w0 = Wb[(2 * wp) * 64 + n];
        float w1 = Wb[(2 * wp + 1) * 64 + n];
        float l0, l1;
        uint32_t h = bfpack(w0, w1, l0, l1);
        int pos = (wp & 3) * 8 + (wp >> 2);
        WTH[n * AROW + pos] = h;
        WTL[n * AROW + pos] = bfpack2(l0, l1);
    }
    __syncthreads();

    // ---- W fragments to registers (held for whole kernel) ----
    uint32_t wh0[4][4], wh1[4][4], wl0[4][4], wl1[4][4];
#pragma unroll
    for (int kt = 0; kt < 4; kt++)
#pragma unroll
        for (int nt = 0; nt < 4; nt++) {
            int n = nh * 32 + nt * 8 + gid;
            uint2 wh = *(const uint2*)&WTH[n * AROW + tig * 8 + kt * 2];
            uint2 wl = *(const uint2*)&WTL[n * AROW + tig * 8 + kt * 2];
            wh0[kt][nt] = wh.x;
            wh1[kt][nt] = wh.y;
            wl0[kt][nt] = wl.x;
            wl1[kt][nt] = wl.y;
        }
    float bias[4][2];
#pragma unroll
    for (int nt = 0; nt < 4; nt++) {
        int c0 = nh * 32 + nt * 8 + tig * 2;
        bias[nt][0] = bb[c0];
        bias[nt][1] = bb[c0 + 1];
    }
    __syncthreads();   // done with WTH/WTL region (aliases staging)

    int stride = gridDim.x;
    int ge = tid >> 1, gp = tid & 1;   // gather: 2 threads/edge, 32 vals each

    for (int t = tile_begin + (int)blockIdx.x; t < tile_end; t += stride) {
        // ---- 0. tile indices ----
        if (tid < TILE_E) {
            long long e = (long long)t * TILE_E + tid;
            ds[tid] = (e < E) ? DST[e] : -1;
            ss[tid] = (e < E) ? SRC[e] : 0;
        }
        __syncthreads();

        // ---- 1. gather + relu + bf16 split -> AH/AL (permuted layout) ----
        {
            int d = ds[ge], s = ss[ge];
            uint32_t hw[16], lw[16];
            if (d >= 0) {
                const float4* ap =
                    (const float4*)&g_A[(size_t)d * 64 + gp * 32];
                const float4* bp =
                    (const float4*)&g_B[(size_t)s * 64 + gp * 32];
#pragma unroll
                for (int q = 0; q < 8; q++) {
                    float4 av = ap[q], bv = bp[q];
                    float v0 = fmaxf(av.x + bv.x, 0.f);
                    float v1 = fmaxf(av.y + bv.y, 0.f);
                    float v2 = fmaxf(av.z + bv.z, 0.f);
                    float v3 = fmaxf(av.w + bv.w, 0.f);
                    float l0, l1;
                    hw[2 * q] = bfpack(v0, v1, l0, l1);
                    lw[2 * q] = bfpack2(l0, l1);
                    hw[2 * q + 1] = bfpack(v2, v3, l0, l1);
                    lw[2 * q + 1] = bfpack2(l0, l1);
                }
            } else {
#pragma unroll
                for (int j = 0; j < 16; j++) { hw[j] = 0u; lw[j] = 0u; }
            }
            // orig word w = gp*16 + m + 4j -> pos = m*8 + gp*4 + j
            uint32_t* ah = AH + ge * AROW + gp * 4;
            uint32_t* al = AL + ge * AROW + gp * 4;
#pragma unroll
            for (int m = 0; m < 4; m++) {
                *(uint4*)(ah + m * 8) =
                    make_uint4(hw[m], hw[m + 4], hw[m + 8], hw[m + 12]);
                *(uint4*)(al + m * 8) =
                    make_uint4(lw[m], lw[m + 4], lw[m + 8], lw[m + 12]);
            }
        }
        __syncthreads();

        // ---- 2. MMA: 2 patches x 4 kt x 4 nt x 3 terms, fp32 accum ----
        float acc[2][4][4];
#pragma unroll
        for (int pa = 0; pa < 2; pa++)
#pragma unroll
            for (int nt = 0; nt < 4; nt++)
#pragma unroll
                for (int j = 0; j < 4; j++) acc[pa][nt][j] = 0.f;

#pragma unroll
        for (int pa = 0; pa < 2; pa++) {
            int erow = eg * 32 + pa * 16 + gid;
#pragma unroll
            for (int kt = 0; kt < 4; kt++) {
                int fo = tig * 8 + kt * 2;
                uint2 a02 = *(const uint2*)&AH[erow * AROW + fo];
                uint2 a13 = *(const uint2*)&AH[(erow + 8) * AROW + fo];
                uint2 l02 = *(const uint2*)&AL[erow * AROW + fo];
                uint2 l13 = *(const uint2*)&AL[(erow + 8) * AROW + fo];
#pragma unroll
                for (int nt = 0; nt < 4; nt++) {
                    MMAB16(acc[pa][nt], a02.x, a13.x, a02.y, a13.y,
                           wh0[kt][nt], wh1[kt][nt]);
                    MMAB16(acc[pa][nt], a02.x, a13.x, a02.y, a13.y,
                           wl0[kt][nt], wl1[kt][nt]);
                    MMAB16(acc[pa][nt], l02.x, l13.x, l02.y, l13.y,
                           wh0[kt][nt], wh1[kt][nt]);
                }
            }
        }

        // ---- 3. bias + relu -> staging [col][edge] stride 264 ----
#pragma unroll
        for (int pa = 0; pa < 2; pa++) {
            int erow = eg * 32 + pa * 16 + gid;
#pragma unroll
            for (int nt = 0; nt < 4; nt++) {
                int c0 = nh * 32 + nt * 8 + tig * 2;
                STG[c0 * 264 + erow] =
                    fmaxf(acc[pa][nt][0] + bias[nt][0], 0.f);
                STG[(c0 + 1) * 264 + erow] =
                    fmaxf(acc[pa][nt][1] + bias[nt][1], 0.f);
                STG[c0 * 264 + erow + 8] =
                    fmaxf(acc[pa][nt][2] + bias[nt][0], 0.f);
                STG[(c0 + 1) * 264 + erow + 8] =
                    fmaxf(acc[pa][nt][3] + bias[nt][1], 0.f);
            }
        }
        __syncthreads();   // STG ready

        // ---- 4. run-dedup atomicMax: 32 sorted edges per thread ----
        {
            int c = tid >> 3;
            int seg = (tid & 7) * 32;
            const float* sp = STG + c * 264 + seg;
            const int* dsc = ds + seg;
            int d = dsc[0];
            float m = sp[0];
#pragma unroll
            for (int q = 0; q < 8; q++) {
                float4 f = *(const float4*)(sp + q * 4);
                float v[4] = {f.x, f.y, f.z, f.w};
#pragma unroll
                for (int j = 0; j < 4; j++) {
                    int idx = q * 4 + j;
                    if (idx == 0) continue;
                    int dn = dsc[idx];
                    if (dn == d) {
                        m = fmaxf(m, v[j]);
                    } else {
                        if (d >= 0)
                            atomicMax(&out[d * 64 + c], __float_as_int(m));
                        d = dn;
                        m = v[j];
                    }
                }
            }
            if (d >= 0) atomicMax(&out[d * 64 + c], __float_as_int(m));
        }
        __syncthreads();   // ds/ss + AH/AL + STG free for next tile
    }
}

// ------------------------------ batchnorm ----------------------------------

__global__ void k_bnstats(int layer, int n) {  // grid 128, block 256
    const int* raw = layer ? g_raw2 : g_raw1;
    int tid = threadIdx.x;
    int c = tid & 63, gq = tid >> 6;
    float s = 0.f, s2 = 0.f;
    for (int r = blockIdx.x * 4 + gq; r < n; r += 512) {
        float v = __int_as_float(raw[r * 64 + c]);
        s += v;
        s2 += v * v;
    }
    __shared__ float sh[256], sh2[256];
    sh[tid] = s;
    sh2[tid] = s2;
    __syncthreads();
    if (gq == 0) {
#pragma unroll
        for (int q = 1; q < 4; q++) {
            s += sh[q * 64 + c];
            s2 += sh2[q * 64 + c];
        }
        g_part[blockIdx.x * 128 + c] = s;
        g_part[blockIdx.x * 128 + 64 + c] = s2;
    }
}

__global__ void k_bnfinal(const float* __restrict__ gamma,
                          const float* __restrict__ beta, int n, int layer) {
    int c = threadIdx.x;
    if (c < 64) {
        float s = 0.f, s2 = 0.f;
        for (int b = 0; b < 128; b++) {
            s += g_part[b * 128 + c];
            s2 += g_part[b * 128 + 64 + c];
        }
        float mean = s / (float)n;
        float var = s2 / (float)n - mean * mean;
        float sc = gamma[c] * rsqrtf(var + 1e-5f);
        g_scale[layer * 64 + c] = sc;
        g_shift[layer * 64 + c] = beta[c] - mean * sc;
    }
}

// ---------------------- pooling + BN2 finalize + h write --------------------

__global__ __launch_bounds__(256) void k_pool(
    const int* __restrict__ batch, int n, int G,
    float* __restrict__ outh, float* __restrict__ outg) {
    int g = blockIdx.x;
    int lo = 0, hi = n;
    while (lo < hi) {
        int mid = (lo + hi) >> 1;
        if (batch[mid] < g) lo = mid + 1; else hi = mid;
    }
    int start = lo;
    hi = n;
    while (lo < hi) {
        int mid = (lo + hi) >> 1;
        if (batch[mid] < g + 1) lo = mid + 1; else hi = mid;
    }
    int end = lo;

    int tid = threadIdx.x;
    int c = tid & 63, gq = tid >> 6;
    float sc = g_scale[64 + c], sh = g_shift[64 + c];
    float s = 0.f, m = __int_as_float(NEG_INF_BITS);
    for (int r = start + gq; r < end; r += 4) {
        float v = __int_as_float(g_raw2[r * 64 + c]) * sc + sh;
        outh[(size_t)r * 64 + c] = v;
        s += v;
        m = fmaxf(m, v);
    }
    __shared__ float shs[256], shm[256];
    shs[tid] = s;
    shm[tid] = m;
    __syncthreads();
    if (gq == 0) {
#pragma unroll
        for (int q = 1; q < 4; q++) {
            s += shs[q * 64 + c];
            m = fmaxf(m, shm[q * 64 + c]);
        }
        int cnt = end - start;
        float mean = s / fmaxf((float)cnt, 1.f);
        float mx = (cnt > 0) ? m : __int_as_float(NEG_INF_BITS);
        outg[g * 128 + c] = mean;
        outg[g * 128 + 64 + c] = mx;
    }
}

// ------------------------------- launch ------------------------------------

extern "C" void kernel_launch(void* const* d_in, const int* in_sizes, int n_in,
                              void* d_out, int out_size) {
    const float* x    = (const float*)d_in[0];
    const int*   ei   = (const int*)d_in[1];
    const int*   batch = (const int*)d_in[2];
    const float* W1a = (const float*)d_in[3];
    const float* b1a = (const float*)d_in[4];
    const float* W1b = (const float*)d_in[5];
    const float* b1b = (const float*)d_in[6];
    const float* g1  = (const float*)d_in[7];
    const float* be1 = (const float*)d_in[8];
    const float* W2a = (const float*)d_in[9];
    const float* b2a = (const float*)d_in[10];
    const float* W2b = (const float*)d_in[11];
    const float* b2b = (const float*)d_in[12];
    const float* g2  = (const float*)d_in[13];
    const float* be2 = (const float*)d_in[14];

    int N = in_sizes[0] / 64;
    int E = in_sizes[1] / 2;
    int G = (out_size - N * 64) / 128;
    const int* src = ei;
    const int* dst = ei + E;

    float* outh = (float*)d_out;
    float* outg = outh + (size_t)N * 64;

    cudaFuncSetAttribute(k_edge_mma,
                         cudaFuncAttributeMaxDynamicSharedMemorySize,
                         SM_EDGE_TOTAL);

    int ntiles = (E + TILE_E - 1) / TILE_E;

    // [0] init raw1 + zero counters
    k_init_raw<<<2048, 256>>>(0, N * 64, N);
    // [1] node linear for layer 1
    k_nodelin<<<(N + 31) / 32, 256>>>(x, 0, W1a, b1a, N);
    // [2] histogram (independent of probe)
    k_hist<<<1024, 256>>>(dst, E);
    // [3] ncu probe: 100 tiles over the RAW edge list (subset-max, neutral)
    k_edge_mma<<<100, 512, SM_EDGE_TOTAL>>>(W1b, b1b, src, dst, 1, 0, 100, E, 0);

    // --- rest of the counting sort ---
    int nch = (N + 1023) / 1024;
    k_scan1<<<nch, 1024>>>(N);
    k_scan2<<<1, 64>>>(nch);
    k_scan3<<<(N + 255) / 256, 256>>>(N);
    k_scatter<<<1024, 256>>>(src, dst, E);

    // --- layer 1 (full pass over sorted edges) ---
    k_edge_mma<<<152, 512, SM_EDGE_TOTAL>>>(W1b, b1b, src, dst, 0, 0, ntiles,
                                            E, 0);
    k_bnstats<<<128, 256>>>(0, N);
    k_bnfinal<<<1, 64>>>(g1, be1, N, 0);

    // --- layer 2 (BN1 folded into the node linear via g_scale/g_shift) ---
    k_nodelin<<<(N + 31) / 32, 256>>>(nullptr, 1, W2a, b2a, N);
    k_init_raw<<<2048, 256>>>(1, N * 64, 0);
    k_edge_mma<<<152, 512, SM_EDGE_TOTAL>>>(W2b, b2b, src, dst, 0, 0, ntiles,
                                            E, 1);
    k_bnstats<<<128, 256>>>(1, N);
    k_bnfinal<<<1, 64>>>(g2, be2, N, 1);

    // --- BN2 finalize + h write + mean/max pooling ---
    k_pool<<<G, 256>>>(batch, N, G, outh, outg);
}

// round 12
// speedup vs baseline: 1.0754x; 1.0754x over previous
#include <cuda_runtime.h>
#include <cuda_fp16.h>
#include <cstdint>

// ---------------------------------------------------------------------------
// GNNEncoder: 2x (EdgeConv -> BatchNorm) + mean/max pooling
//
// Algebra: concat[x_i, x_j-x_i] @ Wa = x_i@(Wtop-Wbot) + x_j@Wbot
//   => per-node A[i], B[j]; per-edge layer-1 is A[dst]+B[src]
// BatchNorm folded into next node GEMM / pooling. Edges counting-sorted by
// dst => run-dedup atomicMax epilogue.
// R12: latency-bound at occupancy 1 (issue ~13%, tensor ~4%) => small CTAs:
//      TILE_E 64, 256 threads, 34.5 KB SMEM, occupancy 3. Independent
//      per-CTA barriers overlap the serialized phases across CTAs.
//      bf16 3-term split, permuted-k fragment layout (unchanged numerics).
// ---------------------------------------------------------------------------

#define HC 64
#define NMAX 50000
#define EMAX 1600000
#define NEG_INF_BITS ((int)0xFF800000u)

typedef unsigned long long u64;

#define FMA2(d, a, b, c) \
    asm("fma.rn.f32x2 %0, %1, %2, %3;" : "=l"(d) : "l"(a), "l"(b), "l"(c))
#define PACK2(d, v) \
    asm("mov.b64 %0, {%1, %1};" : "=l"(d) : "r"(v))
#define UNPACK2(lo, hi, v) \
    asm("mov.b64 {%0, %1}, %2;" : "=r"(lo), "=r"(hi) : "l"(v))

// fp32-accumulator bf16 HMMA
#define MMAB16(c, a0, a1, a2, a3, b0, b1)                                    \
    asm volatile(                                                            \
        "mma.sync.aligned.m16n8k16.row.col.f32.bf16.bf16.f32 "               \
        "{%0,%1,%2,%3}, {%4,%5,%6,%7}, {%8,%9}, {%0,%1,%2,%3};"              \
        : "+f"((c)[0]), "+f"((c)[1]), "+f"((c)[2]), "+f"((c)[3])             \
        : "r"(a0), "r"(a1), "r"(a2), "r"(a3), "r"(b0), "r"(b1))

__device__ int   g_cnt[NMAX];
__device__ int   g_chunk[256];
__device__ int   g_src[EMAX];
__device__ int   g_dst[EMAX];
__device__ float g_A[NMAX * HC];
__device__ float g_B[NMAX * HC];
__device__ int   g_raw1[NMAX * HC];   // float bits, atomicMax as signed int
__device__ int   g_raw2[NMAX * HC];
__device__ float g_part[128 * 2 * HC];
__device__ float g_scale[2 * HC];
__device__ float g_shift[2 * HC];

// ---------------------------- small utilities ------------------------------

__global__ void k_init_raw(int layer, int n, int ncnt) {
    int* raw = layer ? g_raw2 : g_raw1;
    for (int i = blockIdx.x * blockDim.x + threadIdx.x; i < n;
         i += gridDim.x * blockDim.x) {
        raw[i] = NEG_INF_BITS;
        if (i < ncnt) g_cnt[i] = 0;
    }
}

__global__ void k_hist(const int* __restrict__ dst, int E) {
    for (int e = blockIdx.x * blockDim.x + threadIdx.x; e < E;
         e += gridDim.x * blockDim.x)
        atomicAdd(&g_cnt[dst[e]], 1);
}

__global__ void k_scan1(int n) {  // blockDim = 1024
    __shared__ int s[1024];
    int i = blockIdx.x * 1024 + threadIdx.x;
    int v = (i < n) ? g_cnt[i] : 0;
    s[threadIdx.x] = v;
    __syncthreads();
    for (int off = 1; off < 1024; off <<= 1) {
        int t = 0;
        if (threadIdx.x >= off) t = s[threadIdx.x - off];
        __syncthreads();
        s[threadIdx.x] += t;
        __syncthreads();
    }
    if (i < n) g_cnt[i] = s[threadIdx.x] - v;   // exclusive within chunk
    if (threadIdx.x == 1023) g_chunk[blockIdx.x] = s[1023];
}

__global__ void k_scan2(int nch) {  // blockDim = 64, nch <= 64
    __shared__ int s[64];
    int i = threadIdx.x;
    int v = (i < nch) ? g_chunk[i] : 0;
    s[i] = v;
    __syncthreads();
    for (int off = 1; off < 64; off <<= 1) {
        int t = (i >= off) ? s[i - off] : 0;
        __syncthreads();
        s[i] += t;
        __syncthreads();
    }
    if (i < nch) g_chunk[i] = s[i] - v;   // exclusive
}

__global__ void k_scan3(int n) {
    int i = blockIdx.x * blockDim.x + threadIdx.x;
    if (i < n) g_cnt[i] += g_chunk[i >> 10];
}

__global__ void k_scatter(const int* __restrict__ src,
                          const int* __restrict__ dst, int E) {
    for (int e = blockIdx.x * blockDim.x + threadIdx.x; e < E;
         e += gridDim.x * blockDim.x) {
        int d = dst[e];
        int p = atomicAdd(&g_cnt[d], 1);
        g_src[p] = src[e];
        g_dst[p] = d;
    }
}

// ------------------------- per-node linear (A, B) ---------------------------

__global__ __launch_bounds__(256) void k_nodelin(
    const float* __restrict__ xin, int use_raw,
    const float* __restrict__ Wa,  // [128,64] row-major
    const float* __restrict__ ba, int n) {
    __shared__ float Ws[128 * 64];
    __shared__ float xs[32 * 65];
    int tid = threadIdx.x;
    for (int i = tid; i < 128 * 64; i += 256) Ws[i] = Wa[i];

    int row0 = blockIdx.x * 32;
    for (int i = tid; i < 32 * 64; i += 256) {
        int r = i >> 6, k = i & 63;
        int row = row0 + r;
        float v = 0.f;
        if (row < n) {
            if (use_raw)
                v = __int_as_float(g_raw1[row * 64 + k]) * g_scale[k] + g_shift[k];
            else
                v = xin[row * 64 + k];
        }
        xs[r * 65 + k] = v;
    }
    __syncthreads();

    int r = tid & 31, cg = tid >> 5;
    int c0 = cg * 8;
    u64 a2[4], b2[4];
#pragma unroll
    for (int j = 0; j < 4; j++) { a2[j] = 0ull; b2[j] = 0ull; }

#pragma unroll 8
    for (int k = 0; k < 64; k++) {
        float xv = xs[r * 65 + k];
        u64 xp;
        PACK2(xp, __float_as_uint(xv));
        ulonglong2 t0 = *(const ulonglong2*)&Ws[k * 64 + c0];
        ulonglong2 t1 = *(const ulonglong2*)&Ws[k * 64 + c0 + 4];
        ulonglong2 q0 = *(const ulonglong2*)&Ws[(64 + k) * 64 + c0];
        ulonglong2 q1 = *(const ulonglong2*)&Ws[(64 + k) * 64 + c0 + 4];
        FMA2(a2[0], xp, t0.x, a2[0]);
        FMA2(a2[1], xp, t0.y, a2[1]);
        FMA2(a2[2], xp, t1.x, a2[2]);
        FMA2(a2[3], xp, t1.y, a2[3]);
        FMA2(b2[0], xp, q0.x, b2[0]);
        FMA2(b2[1], xp, q0.y, b2[1]);
        FMA2(b2[2], xp, q1.x, b2[2]);
        FMA2(b2[3], xp, q1.y, b2[3]);
    }
    int row = row0 + r;
    if (row < n) {
        float a[8], b[8];
#pragma unroll
        for (int j = 0; j < 4; j++) {
            unsigned int lo, hi;
            UNPACK2(lo, hi, a2[j]);
            a[2 * j] = __uint_as_float(lo);
            a[2 * j + 1] = __uint_as_float(hi);
            UNPACK2(lo, hi, b2[j]);
            b[2 * j] = __uint_as_float(lo);
            b[2 * j + 1] = __uint_as_float(hi);
        }
#pragma unroll
        for (int j = 0; j < 8; j++) {
            float bb = ba[c0 + j];
            g_A[row * 64 + c0 + j] = a[j] - b[j] + bb;
            g_B[row * 64 + c0 + j] = b[j];
        }
    }
}

// ---------- edge kernel (64-edge tiles, 256 threads, occupancy 3) -----------
// k-order permuted identically in A and W tiles (dot products invariant):
// orig k-pair word w stored at pos = (w&3)*8 + (w>>2); MMA thread fragments
// contiguous (LDS.64). 8 warps: warp (eg 0..3, nh 0..1) = 16 edges x 32 cols.

#define TILE_E 64
#define AROW 34                             // u32 stride per edge row (pad)
// dynamic smem (bytes)
#define SMO_DS   0                          // int [64]
#define SMO_SS   256                        // int [64]
#define SMO_AH   512                        // [64][34] u32 = 8704 B
#define SMO_AL   9216                       // 8704 B
#define SMO_STG  17920                      // [64][68] f32 = 17408 B
#define SMO_WTH  17920                      // init-only alias, [64][34] u32
#define SMO_WTL  26624                      // init-only alias
#define SM_EDGE_TOTAL 35328

// bf16 split: hi = top 16 bits (truncate), lo = (x - hi) truncated again.
__device__ __forceinline__ uint32_t bfpack(float x0, float x1,
                                           float& l0, float& l1) {
    uint32_t u0 = __float_as_uint(x0), u1 = __float_as_uint(x1);
    l0 = x0 - __uint_as_float(u0 & 0xFFFF0000u);
    l1 = x1 - __uint_as_float(u1 & 0xFFFF0000u);
    return __byte_perm(u0, u1, 0x7632);
}
__device__ __forceinline__ uint32_t bfpack2(float l0, float l1) {
    return __byte_perm(__float_as_uint(l0), __float_as_uint(l1), 0x7632);
}

__global__ __launch_bounds__(256, 3) void k_edge_mma(
    const float* __restrict__ Wb,   // [64k][64n]
    const float* __restrict__ bb,   // [64]
    const int* __restrict__ psrc, const int* __restrict__ pdst, int use_p,
    int tile_begin, int tile_end, int E, int layer) {
    extern __shared__ char sm[];
    int* ds = (int*)(sm + SMO_DS);
    int* ss = (int*)(sm + SMO_SS);
    uint32_t* AH = (uint32_t*)(sm + SMO_AH);
    uint32_t* AL = (uint32_t*)(sm + SMO_AL);
    float* STG = (float*)(sm + SMO_STG);
    uint32_t* WTH = (uint32_t*)(sm + SMO_WTH);
    uint32_t* WTL = (uint32_t*)(sm + SMO_WTL);

    const int* SRC = use_p ? psrc : g_src;
    const int* DST = use_p ? pdst : g_dst;

    int* out = layer ? g_raw2 : g_raw1;
    int tid = threadIdx.x;
    int wid = tid >> 5, lid = tid & 31;
    int gid = lid >> 2, tig = lid & 3;
    int eg = wid >> 1, nh = wid & 1;

    // ---- W split -> SMEM in permuted-k fragment layout ----
    for (int i = tid; i < 64 * 32; i += 256) {
        int n = i >> 5, wp = i & 31;           // orig k-pair index wp
        float w0 = Wb[(2 * wp) * 64 + n];
        float w1 = Wb[(2 * wp + 1) * 64 + n];
        float l0, l1;
        uint32_t h = bfpack(w0, w1, l0, l1);
        int pos = (wp & 3) * 8 + (wp >> 2);
        WTH[n * AROW + pos] = h;
        WTL[n * AROW + pos] = bfpack2(l0, l1);
    }
    __syncthreads();

    // ---- W fragments to registers (held for whole kernel) ----
    uint32_t wh0[4][4], wh1[4][4], wl0[4][4], wl1[4][4];
#pragma unroll
    for (int kt = 0; kt < 4; kt++)
#pragma unroll
        for (int nt = 0; nt < 4; nt++) {
            int n = nh * 32 + nt * 8 + gid;
            uint2 wh = *(const uint2*)&WTH[n * AROW + tig * 8 + kt * 2];
            uint2 wl = *(const uint2*)&WTL[n * AROW + tig * 8 + kt * 2];
            wh0[kt][nt] = wh.x;
            wh1[kt][nt] = wh.y;
            wl0[kt][nt] = wl.x;
            wl1[kt][nt] = wl.y;
        }
    float bias[4][2];
#pragma unroll
    for (int nt = 0; nt < 4; nt++) {
        int c0 = nh * 32 + nt * 8 + tig * 2;
        bias[nt][0] = bb[c0];
        bias[nt][1] = bb[c0 + 1];
    }
    __syncthreads();   // done with WTH/WTL region (aliases staging)

    int stride = gridDim.x;
    int ge = tid >> 2, gp = tid & 3;   // gather: 4 threads/edge, 16 vals each

    for (int t = tile_begin + (int)blockIdx.x; t < tile_end; t += stride) {
        // ---- 0. tile indices ----
        if (tid < TILE_E) {
            long long e = (long long)t * TILE_E + tid;
            ds[tid] = (e < E) ? DST[e] : -1;
            ss[tid] = (e < E) ? SRC[e] : 0;
        }
        __syncthreads();

        // ---- 1. gather + relu + bf16 split -> AH/AL (permuted layout) ----
        {
            int d = ds[ge], s = ss[ge];
            uint32_t hw[8], lw[8];
            if (d >= 0) {
                const float4* ap =
                    (const float4*)&g_A[(size_t)d * 64 + gp * 16];
                const float4* bp =
                    (const float4*)&g_B[(size_t)s * 64 + gp * 16];
#pragma unroll
                for (int q = 0; q < 4; q++) {
                    float4 av = ap[q], bv = bp[q];
                    float v0 = fmaxf(av.x + bv.x, 0.f);
                    float v1 = fmaxf(av.y + bv.y, 0.f);
                    float v2 = fmaxf(av.z + bv.z, 0.f);
                    float v3 = fmaxf(av.w + bv.w, 0.f);
                    float l0, l1;
                    hw[2 * q] = bfpack(v0, v1, l0, l1);
                    lw[2 * q] = bfpack2(l0, l1);
                    hw[2 * q + 1] = bfpack(v2, v3, l0, l1);
                    lw[2 * q + 1] = bfpack2(l0, l1);
                }
            } else {
#pragma unroll
                for (int j = 0; j < 8; j++) { hw[j] = 0u; lw[j] = 0u; }
            }
            // orig words gp*8+jj and gp*8+jj+4 -> positions jj*8+gp*2, +1
            uint32_t* ah = AH + ge * AROW + gp * 2;
            uint32_t* al = AL + ge * AROW + gp * 2;
#pragma unroll
            for (int jj = 0; jj < 4; jj++) {
                *(uint2*)(ah + jj * 8) = make_uint2(hw[jj], hw[jj + 4]);
                *(uint2*)(al + jj * 8) = make_uint2(lw[jj], lw[jj + 4]);
            }
        }
        __syncthreads();

        // ---- 2. MMA: 4 kt x 4 nt x 3 terms, fp32 accum ----
        float acc[4][4];
#pragma unroll
        for (int nt = 0; nt < 4; nt++)
#pragma unroll
            for (int j = 0; j < 4; j++) acc[nt][j] = 0.f;

        int erow = eg * 16 + gid;
#pragma unroll
        for (int kt = 0; kt < 4; kt++) {
            int fo = tig * 8 + kt * 2;
            uint2 a02 = *(const uint2*)&AH[erow * AROW + fo];
            uint2 a13 = *(const uint2*)&AH[(erow + 8) * AROW + fo];
            uint2 l02 = *(const uint2*)&AL[erow * AROW + fo];
            uint2 l13 = *(const uint2*)&AL[(erow + 8) * AROW + fo];
#pragma unroll
            for (int nt = 0; nt < 4; nt++) {
                MMAB16(acc[nt], a02.x, a13.x, a02.y, a13.y,
                       wh0[kt][nt], wh1[kt][nt]);
                MMAB16(acc[nt], a02.x, a13.x, a02.y, a13.y,
                       wl0[kt][nt], wl1[kt][nt]);
                MMAB16(acc[nt], l02.x, l13.x, l02.y, l13.y,
                       wh0[kt][nt], wh1[kt][nt]);
            }
        }

        // ---- 3. bias + relu -> staging [col][edge] stride 68 ----
#pragma unroll
        for (int nt = 0; nt < 4; nt++) {
            int c0 = nh * 32 + nt * 8 + tig * 2;
            STG[c0 * 68 + erow] = fmaxf(acc[nt][0] + bias[nt][0], 0.f);
            STG[(c0 + 1) * 68 + erow] = fmaxf(acc[nt][1] + bias[nt][1], 0.f);
            STG[c0 * 68 + erow + 8] = fmaxf(acc[nt][2] + bias[nt][0], 0.f);
            STG[(c0 + 1) * 68 + erow + 8] = fmaxf(acc[nt][3] + bias[nt][1], 0.f);
        }
        __syncthreads();   // STG ready

        // ---- 4. run-dedup atomicMax: 16 sorted edges per thread ----
        {
            int c = tid >> 2;
            int seg = (tid & 3) * 16;
            const float* sp = STG + c * 68 + seg;
            const int* dsc = ds + seg;
            float v[16];
#pragma unroll
            for (int q = 0; q < 4; q++) {
                float4 f = *(const float4*)(sp + q * 4);
                v[q * 4 + 0] = f.x; v[q * 4 + 1] = f.y;
                v[q * 4 + 2] = f.z; v[q * 4 + 3] = f.w;
            }
            int d = dsc[0];
            float m = v[0];
#pragma unroll
            for (int i = 1; i < 16; i++) {
                int dn = dsc[i];
                if (dn == d) {
                    m = fmaxf(m, v[i]);
                } else {
                    if (d >= 0) atomicMax(&out[d * 64 + c], __float_as_int(m));
                    d = dn;
                    m = v[i];
                }
            }
            if (d >= 0) atomicMax(&out[d * 64 + c], __float_as_int(m));
        }
        __syncthreads();   // ds/ss + AH/AL + STG free for next tile
    }
}

// ------------------------------ batchnorm ----------------------------------

__global__ void k_bnstats(int layer, int n) {  // grid 128, block 256
    const int* raw = layer ? g_raw2 : g_raw1;
    int tid = threadIdx.x;
    int c = tid & 63, gq = tid >> 6;
    float s = 0.f, s2 = 0.f;
    for (int r = blockIdx.x * 4 + gq; r < n; r += 512) {
        float v = __int_as_float(raw[r * 64 + c]);
        s += v;
        s2 += v * v;
    }
    __shared__ float sh[256], sh2[256];
    sh[tid] = s;
    sh2[tid] = s2;
    __syncthreads();
    if (gq == 0) {
#pragma unroll
        for (int q = 1; q < 4; q++) {
            s += sh[q * 64 + c];
            s2 += sh2[q * 64 + c];
        }
        g_part[blockIdx.x * 128 + c] = s;
        g_part[blockIdx.x * 128 + 64 + c] = s2;
    }
}

__global__ void k_bnfinal(const float* __restrict__ gamma,
                          const float* __restrict__ beta, int n, int layer) {
    int c = threadIdx.x;
    if (c < 64) {
        float s = 0.f, s2 = 0.f;
        for (int b = 0; b < 128; b++) {
            s += g_part[b * 128 + c];
            s2 += g_part[b * 128 + 64 + c];
        }
        float mean = s / (float)n;
        float var = s2 / (float)n - mean * mean;
        float sc = gamma[c] * rsqrtf(var + 1e-5f);
        g_scale[layer * 64 + c] = sc;
        g_shift[layer * 64 + c] = beta[c] - mean * sc;
    }
}

// ---------------------- pooling + BN2 finalize + h write --------------------

__global__ __launch_bounds__(256) void k_pool(
    const int* __restrict__ batch, int n, int G,
    float* __restrict__ outh, float* __restrict__ outg) {
    int g = blockIdx.x;
    int lo = 0, hi = n;
    while (lo < hi) {
        int mid = (lo + hi) >> 1;
        if (batch[mid] < g) lo = mid + 1; else hi = mid;
    }
    int start = lo;
    hi = n;
    while (lo < hi) {
        int mid = (lo + hi) >> 1;
        if (batch[mid] < g + 1) lo = mid + 1; else hi = mid;
    }
    int end = lo;

    int tid = threadIdx.x;
    int c = tid & 63, gq = tid >> 6;
    float sc = g_scale[64 + c], sh = g_shift[64 + c];
    float s = 0.f, m = __int_as_float(NEG_INF_BITS);
    for (int r = start + gq; r < end; r += 4) {
        float v = __int_as_float(g_raw2[r * 64 + c]) * sc + sh;
        outh[(size_t)r * 64 + c] = v;
        s += v;
        m = fmaxf(m, v);
    }
    __shared__ float shs[256], shm[256];
    shs[tid] = s;
    shm[tid] = m;
    __syncthreads();
    if (gq == 0) {
#pragma unroll
        for (int q = 1; q < 4; q++) {
            s += shs[q * 64 + c];
            m = fmaxf(m, shm[q * 64 + c]);
        }
        int cnt = end - start;
        float mean = s / fmaxf((float)cnt, 1.f);
        float mx = (cnt > 0) ? m : __int_as_float(NEG_INF_BITS);
        outg[g * 128 + c] = mean;
        outg[g * 128 + 64 + c] = mx;
    }
}

// ------------------------------- launch ------------------------------------

extern "C" void kernel_launch(void* const* d_in, const int* in_sizes, int n_in,
                              void* d_out, int out_size) {
    const float* x    = (const float*)d_in[0];
    const int*   ei   = (const int*)d_in[1];
    const int*   batch = (const int*)d_in[2];
    const float* W1a = (const float*)d_in[3];
    const float* b1a = (const float*)d_in[4];
    const float* W1b = (const float*)d_in[5];
    const float* b1b = (const float*)d_in[6];
    const float* g1  = (const float*)d_in[7];
    const float* be1 = (const float*)d_in[8];
    const float* W2a = (const float*)d_in[9];
    const float* b2a = (const float*)d_in[10];
    const float* W2b = (const float*)d_in[11];
    const float* b2b = (const float*)d_in[12];
    const float* g2  = (const float*)d_in[13];
    const float* be2 = (const float*)d_in[14];

    int N = in_sizes[0] / 64;
    int E = in_sizes[1] / 2;
    int G = (out_size - N * 64) / 128;
    const int* src = ei;
    const int* dst = ei + E;

    float* outh = (float*)d_out;
    float* outg = outh + (size_t)N * 64;

    cudaFuncSetAttribute(k_edge_mma,
                         cudaFuncAttributeMaxDynamicSharedMemorySize,
                         SM_EDGE_TOTAL);

    int ntiles = (E + TILE_E - 1) / TILE_E;
    int egrid = 152 * 4;

    // [0] init raw1 + zero counters
    k_init_raw<<<2048, 256>>>(0, N * 64, N);
    // [1] node linear for layer 1
    k_nodelin<<<(N + 31) / 32, 256>>>(x, 0, W1a, b1a, N);
    // [2] histogram (independent of probe)
    k_hist<<<1024, 256>>>(dst, E);
    // [3] ncu probe: 400 tiles over the RAW edge list (subset-max, neutral)
    k_edge_mma<<<100, 256, SM_EDGE_TOTAL>>>(W1b, b1b, src, dst, 1, 0, 400, E, 0);

    // --- rest of the counting sort ---
    int nch = (N + 1023) / 1024;
    k_scan1<<<nch, 1024>>>(N);
    k_scan2<<<1, 64>>>(nch);
    k_scan3<<<(N + 255) / 256, 256>>>(N);
    k_scatter<<<1024, 256>>>(src, dst, E);

    // --- layer 1 (full pass over sorted edges) ---
    k_edge_mma<<<egrid, 256, SM_EDGE_TOTAL>>>(W1b, b1b, src, dst, 0, 0, ntiles,
                                              E, 0);
    k_bnstats<<<128, 256>>>(0, N);
    k_bnfinal<<<1, 64>>>(g1, be1, N, 0);

    // --- layer 2 (BN1 folded into the node linear via g_scale/g_shift) ---
    k_nodelin<<<(N + 31) / 32, 256>>>(nullptr, 1, W2a, b2a, N);
    k_init_raw<<<2048, 256>>>(1, N * 64, 0);
    k_edge_mma<<<egrid, 256, SM_EDGE_TOTAL>>>(W2b, b2b, src, dst, 0, 0, ntiles,
                                              E, 1);
    k_bnstats<<<128, 256>>>(1, N);
    k_bnfinal<<<1, 64>>>(g2, be2, N, 1);

    // --- BN2 finalize + h write + mean/max pooling ---
    k_pool<<<G, 256>>>(batch, N, G, outh, outg);
}

// round 13
// speedup vs baseline: 1.2755x; 1.1860x over previous
#include <cuda_runtime.h>
#include <cuda_fp16.h>
#include <cstdint>

// ---------------------------------------------------------------------------
// GNNEncoder: 2x (EdgeConv -> BatchNorm) + mean/max pooling
//
// Algebra: concat[x_i, x_j-x_i] @ Wa = x_i@(Wtop-Wbot) + x_j@Wbot
//   => per-node A[i], B[j]; per-edge layer-1 is A[dst]+B[src]
// BatchNorm folded into next node GEMM / pooling. Edges counting-sorted by
// dst => run-dedup atomicMax epilogue.
// R13: edge kernel is MMA-issue-bound (HMMA rt~32/SMSP; 3-term => 290us/layer
//      floor, matching all measurements). Cut to 2 terms with an asymmetric
//      exact split: W = Wh + Wl (both f16, exact to 2^-23), A rounded once to
//      f16 (error 2^-12). D = a*Wh + a*Wl. MMA count -33%, converts halve.
// ---------------------------------------------------------------------------

#define HC 64
#define NMAX 50000
#define EMAX 1600000
#define NEG_INF_BITS ((int)0xFF800000u)

typedef unsigned long long u64;

#define FMA2(d, a, b, c) \
    asm("fma.rn.f32x2 %0, %1, %2, %3;" : "=l"(d) : "l"(a), "l"(b), "l"(c))
#define PACK2(d, v) \
    asm("mov.b64 %0, {%1, %1};" : "=l"(d) : "r"(v))
#define UNPACK2(lo, hi, v) \
    asm("mov.b64 {%0, %1}, %2;" : "=r"(lo), "=r"(hi) : "l"(v))

// fp32-accumulator f16 HMMA
#define MMAF16(c, a0, a1, a2, a3, b0, b1)                                    \
    asm volatile(                                                            \
        "mma.sync.aligned.m16n8k16.row.col.f32.f16.f16.f32 "                 \
        "{%0,%1,%2,%3}, {%4,%5,%6,%7}, {%8,%9}, {%0,%1,%2,%3};"              \
        : "+f"((c)[0]), "+f"((c)[1]), "+f"((c)[2]), "+f"((c)[3])             \
        : "r"(a0), "r"(a1), "r"(a2), "r"(a3), "r"(b0), "r"(b1))

__device__ __forceinline__ uint32_t pack_h2(__half lo, __half hi) {
    return (uint32_t)__half_as_ushort(lo) |
           ((uint32_t)__half_as_ushort(hi) << 16);
}
__device__ __forceinline__ uint32_t hpack(float x0, float x1) {
    return pack_h2(__float2half_rn(x0), __float2half_rn(x1));
}

__device__ int   g_cnt[NMAX];
__device__ int   g_chunk[256];
__device__ int   g_src[EMAX];
__device__ int   g_dst[EMAX];
__device__ float g_A[NMAX * HC];
__device__ float g_B[NMAX * HC];
__device__ int   g_raw1[NMAX * HC];   // float bits, atomicMax as signed int
__device__ int   g_raw2[NMAX * HC];
__device__ float g_part[128 * 2 * HC];
__device__ float g_scale[2 * HC];
__device__ float g_shift[2 * HC];

// ---------------------------- small utilities ------------------------------

__global__ void k_init_raw(int layer, int n, int ncnt) {
    int* raw = layer ? g_raw2 : g_raw1;
    for (int i = blockIdx.x * blockDim.x + threadIdx.x; i < n;
         i += gridDim.x * blockDim.x) {
        raw[i] = NEG_INF_BITS;
        if (i < ncnt) g_cnt[i] = 0;
    }
}

__global__ void k_hist(const int* __restrict__ dst, int E) {
    for (int e = blockIdx.x * blockDim.x + threadIdx.x; e < E;
         e += gridDim.x * blockDim.x)
        atomicAdd(&g_cnt[dst[e]], 1);
}

__global__ void k_scan1(int n) {  // blockDim = 1024
    __shared__ int s[1024];
    int i = blockIdx.x * 1024 + threadIdx.x;
    int v = (i < n) ? g_cnt[i] : 0;
    s[threadIdx.x] = v;
    __syncthreads();
    for (int off = 1; off < 1024; off <<= 1) {
        int t = 0;
        if (threadIdx.x >= off) t = s[threadIdx.x - off];
        __syncthreads();
        s[threadIdx.x] += t;
        __syncthreads();
    }
    if (i < n) g_cnt[i] = s[threadIdx.x] - v;   // exclusive within chunk
    if (threadIdx.x == 1023) g_chunk[blockIdx.x] = s[1023];
}

__global__ void k_scan2(int nch) {  // blockDim = 64, nch <= 64
    __shared__ int s[64];
    int i = threadIdx.x;
    int v = (i < nch) ? g_chunk[i] : 0;
    s[i] = v;
    __syncthreads();
    for (int off = 1; off < 64; off <<= 1) {
        int t = (i >= off) ? s[i - off] : 0;
        __syncthreads();
        s[i] += t;
        __syncthreads();
    }
    if (i < nch) g_chunk[i] = s[i] - v;   // exclusive
}

__global__ void k_scan3(int n) {
    int i = blockIdx.x * blockDim.x + threadIdx.x;
    if (i < n) g_cnt[i] += g_chunk[i >> 10];
}

__global__ void k_scatter(const int* __restrict__ src,
                          const int* __restrict__ dst, int E) {
    for (int e = blockIdx.x * blockDim.x + threadIdx.x; e < E;
         e += gridDim.x * blockDim.x) {
        int d = dst[e];
        int p = atomicAdd(&g_cnt[d], 1);
        g_src[p] = src[e];
        g_dst[p] = d;
    }
}

// ------------------------- per-node linear (A, B) ---------------------------

__global__ __launch_bounds__(256) void k_nodelin(
    const float* __restrict__ xin, int use_raw,
    const float* __restrict__ Wa,  // [128,64] row-major
    const float* __restrict__ ba, int n) {
    __shared__ float Ws[128 * 64];
    __shared__ float xs[32 * 65];
    int tid = threadIdx.x;
    for (int i = tid; i < 128 * 64; i += 256) Ws[i] = Wa[i];

    int row0 = blockIdx.x * 32;
    for (int i = tid; i < 32 * 64; i += 256) {
        int r = i >> 6, k = i & 63;
        int row = row0 + r;
        float v = 0.f;
        if (row < n) {
            if (use_raw)
                v = __int_as_float(g_raw1[row * 64 + k]) * g_scale[k] + g_shift[k];
            else
                v = xin[row * 64 + k];
        }
        xs[r * 65 + k] = v;
    }
    __syncthreads();

    int r = tid & 31, cg = tid >> 5;
    int c0 = cg * 8;
    u64 a2[4], b2[4];
#pragma unroll
    for (int j = 0; j < 4; j++) { a2[j] = 0ull; b2[j] = 0ull; }

#pragma unroll 8
    for (int k = 0; k < 64; k++) {
        float xv = xs[r * 65 + k];
        u64 xp;
        PACK2(xp, __float_as_uint(xv));
        ulonglong2 t0 = *(const ulonglong2*)&Ws[k * 64 + c0];
        ulonglong2 t1 = *(const ulonglong2*)&Ws[k * 64 + c0 + 4];
        ulonglong2 q0 = *(const ulonglong2*)&Ws[(64 + k) * 64 + c0];
        ulonglong2 q1 = *(const ulonglong2*)&Ws[(64 + k) * 64 + c0 + 4];
        FMA2(a2[0], xp, t0.x, a2[0]);
        FMA2(a2[1], xp, t0.y, a2[1]);
        FMA2(a2[2], xp, t1.x, a2[2]);
        FMA2(a2[3], xp, t1.y, a2[3]);
        FMA2(b2[0], xp, q0.x, b2[0]);
        FMA2(b2[1], xp, q0.y, b2[1]);
        FMA2(b2[2], xp, q1.x, b2[2]);
        FMA2(b2[3], xp, q1.y, b2[3]);
    }
    int row = row0 + r;
    if (row < n) {
        float a[8], b[8];
#pragma unroll
        for (int j = 0; j < 4; j++) {
            unsigned int lo, hi;
            UNPACK2(lo, hi, a2[j]);
            a[2 * j] = __uint_as_float(lo);
            a[2 * j + 1] = __uint_as_float(hi);
            UNPACK2(lo, hi, b2[j]);
            b[2 * j] = __uint_as_float(lo);
            b[2 * j + 1] = __uint_as_float(hi);
        }
#pragma unroll
        for (int j = 0; j < 8; j++) {
            float bb = ba[c0 + j];
            g_A[row * 64 + c0 + j] = a[j] - b[j] + bb;
            g_B[row * 64 + c0 + j] = b[j];
        }
    }
}

// ------------- edge kernel (pipelined, f16 2-term, W split exact) -----------
// k-order permuted identically in A and W tiles (dot products invariant):
// orig k-pair word w stored at pos = (w&3)*8 + (w>>2); MMA thread fragments
// contiguous (LDS.64). 16 warps: warp (eg 0..7, nh 0..1) = 16 edges x 32 cols.

#define TILE_E 128
#define AROW 34                             // u32 stride per edge row (pad)
// dynamic smem (bytes)
#define SMO_DS   0                          // int [2][128]
#define SMO_SS   1024                       // int [2][128]
#define SMO_AH   2048                       // [128][34] u32 = 17408 B
#define SMO_STG  19456                      // [64][132] f32 = 33792 B
#define SMO_WTH  19456                      // init-only alias, [64][34] u32
#define SMO_WTL  28160                      // init-only alias
#define SM_EDGE_TOTAL 53248

__global__ __launch_bounds__(512, 1) void k_edge_mma(
    const float* __restrict__ Wb,   // [64k][64n]
    const float* __restrict__ bb,   // [64]
    const int* __restrict__ psrc, const int* __restrict__ pdst, int use_p,
    int tile_begin, int tile_end, int E, int layer) {
    extern __shared__ char sm[];
    int* dsb = (int*)(sm + SMO_DS);
    int* ssb = (int*)(sm + SMO_SS);
    uint32_t* AH = (uint32_t*)(sm + SMO_AH);
    float* STG = (float*)(sm + SMO_STG);
    uint32_t* WTH = (uint32_t*)(sm + SMO_WTH);
    uint32_t* WTL = (uint32_t*)(sm + SMO_WTL);

    const int* SRC = use_p ? psrc : g_src;
    const int* DST = use_p ? pdst : g_dst;

    int* out = layer ? g_raw2 : g_raw1;
    int tid = threadIdx.x;
    int wid = tid >> 5, lid = tid & 31;
    int gid = lid >> 2, tig = lid & 3;
    int eg = wid & 7, nh = wid >> 3;

    // ---- W exact split -> SMEM in permuted-k fragment layout ----
    for (int i = tid; i < 64 * 32; i += 512) {
        int n = i >> 5, wp = i & 31;           // orig k-pair index wp
        float w0 = Wb[(2 * wp) * 64 + n];
        float w1 = Wb[(2 * wp + 1) * 64 + n];
        __half h0 = __float2half_rn(w0);
        __half h1 = __float2half_rn(w1);
        __half l0 = __float2half_rn(w0 - __half2float(h0));
        __half l1 = __float2half_rn(w1 - __half2float(h1));
        int pos = (wp & 3) * 8 + (wp >> 2);
        WTH[n * AROW + pos] = pack_h2(h0, h1);
        WTL[n * AROW + pos] = pack_h2(l0, l1);
    }
    __syncthreads();

    // ---- W fragments to registers (held for whole kernel) ----
    uint32_t wh0[4][4], wh1[4][4], wl0[4][4], wl1[4][4];
#pragma unroll
    for (int kt = 0; kt < 4; kt++)
#pragma unroll
        for (int nt = 0; nt < 4; nt++) {
            int n = nh * 32 + nt * 8 + gid;
            uint2 wh = *(const uint2*)&WTH[n * AROW + tig * 8 + kt * 2];
            uint2 wl = *(const uint2*)&WTL[n * AROW + tig * 8 + kt * 2];
            wh0[kt][nt] = wh.x;
            wh1[kt][nt] = wh.y;
            wl0[kt][nt] = wl.x;
            wl1[kt][nt] = wl.y;
        }
    float bias[4][2];
#pragma unroll
    for (int nt = 0; nt < 4; nt++) {
        int c0 = nh * 32 + nt * 8 + tig * 2;
        bias[nt][0] = bb[c0];
        bias[nt][1] = bb[c0 + 1];
    }
    __syncthreads();   // done with WTH/WTL region (aliases staging)

    int stride = gridDim.x;
    int t = tile_begin + blockIdx.x;
    if (t >= tile_end) return;

    int ge = tid >> 2, gp = tid & 3;   // gather role: 4 threads/edge, 16 k

    // ---- prologue: ds/ss(t) -> buf0; gather(t); ds/ss(t+stride) -> buf1 ----
    if (tid < TILE_E) {
        int e = t * TILE_E + tid;
        dsb[tid] = (e < E) ? DST[e] : -1;
        ssb[tid] = (e < E) ? SRC[e] : 0;
    }
    __syncthreads();

    float4 ra[4], rb[4];
    {
        int d = dsb[ge], s = ssb[ge];
        if (d >= 0) {
            const float4* ap = (const float4*)&g_A[(size_t)d * 64 + gp * 16];
            const float4* bp = (const float4*)&g_B[(size_t)s * 64 + gp * 16];
#pragma unroll
            for (int q = 0; q < 4; q++) { ra[q] = ap[q]; rb[q] = bp[q]; }
        } else {
#pragma unroll
            for (int q = 0; q < 4; q++) {
                ra[q] = make_float4(0.f, 0.f, 0.f, 0.f);
                rb[q] = ra[q];
            }
        }
    }
    if (tid < TILE_E) {
        long long e = (long long)(t + stride) * TILE_E + tid;
        dsb[128 + tid] = (e < E && (t + stride) < tile_end) ? DST[e] : -1;
        ssb[128 + tid] = (e < E && (t + stride) < tile_end) ? SRC[e] : 0;
    }

    int p = 0;
    for (; t < tile_end; t += stride) {
        int tn = t + stride;

        // ---- 1. convert regs (tile t) -> AH (permuted-k layout) ----
        {
            float v[16];
#pragma unroll
            for (int q = 0; q < 4; q++) {
                v[4 * q + 0] = fmaxf(ra[q].x + rb[q].x, 0.f);
                v[4 * q + 1] = fmaxf(ra[q].y + rb[q].y, 0.f);
                v[4 * q + 2] = fmaxf(ra[q].z + rb[q].z, 0.f);
                v[4 * q + 3] = fmaxf(ra[q].w + rb[q].w, 0.f);
            }
            uint32_t hw[8];
#pragma unroll
            for (int j = 0; j < 8; j++)
                hw[j] = hpack(v[2 * j], v[2 * j + 1]);
            uint32_t* ah = AH + ge * AROW + gp * 2;
#pragma unroll
            for (int jj = 0; jj < 4; jj++)
                *(uint2*)(ah + jj * 8) = make_uint2(hw[jj], hw[jj + 4]);
        }
        __syncthreads();   // AH ready; ds/ss[p^1] (tile tn) visible

        // ---- 2. issue gather LDG for tile tn (hidden under MMA) ----
        if (tn < tile_end) {
            int d = dsb[(p ^ 1) * 128 + ge], s = ssb[(p ^ 1) * 128 + ge];
            if (d >= 0) {
                const float4* ap = (const float4*)&g_A[(size_t)d * 64 + gp * 16];
                const float4* bp = (const float4*)&g_B[(size_t)s * 64 + gp * 16];
#pragma unroll
                for (int q = 0; q < 4; q++) { ra[q] = ap[q]; rb[q] = bp[q]; }
            } else {
#pragma unroll
                for (int q = 0; q < 4; q++) {
                    ra[q] = make_float4(0.f, 0.f, 0.f, 0.f);
                    rb[q] = ra[q];
                }
            }
        }

        // ---- 3. MMA: 2 terms (a*Wh + a*Wl), fp32 accum ----
        float acc[4][4];
#pragma unroll
        for (int nt = 0; nt < 4; nt++)
#pragma unroll
            for (int j = 0; j < 4; j++) acc[nt][j] = 0.f;

        int erow = eg * 16 + gid;
#pragma unroll
        for (int kt = 0; kt < 4; kt++) {
            int fo = tig * 8 + kt * 2;
            uint2 a02 = *(const uint2*)&AH[erow * AROW + fo];
            uint2 a13 = *(const uint2*)&AH[(erow + 8) * AROW + fo];
#pragma unroll
            for (int nt = 0; nt < 4; nt++) {
                MMAF16(acc[nt], a02.x, a13.x, a02.y, a13.y,
                       wh0[kt][nt], wh1[kt][nt]);
                MMAF16(acc[nt], a02.x, a13.x, a02.y, a13.y,
                       wl0[kt][nt], wl1[kt][nt]);
            }
        }

        // ---- bias + relu -> staging [col][edge] stride 132 ----
#pragma unroll
        for (int nt = 0; nt < 4; nt++) {
            int c0 = nh * 32 + nt * 8 + tig * 2;
            STG[c0 * 132 + erow] = fmaxf(acc[nt][0] + bias[nt][0], 0.f);
            STG[(c0 + 1) * 132 + erow] = fmaxf(acc[nt][1] + bias[nt][1], 0.f);
            STG[c0 * 132 + erow + 8] = fmaxf(acc[nt][2] + bias[nt][0], 0.f);
            STG[(c0 + 1) * 132 + erow + 8] = fmaxf(acc[nt][3] + bias[nt][1], 0.f);
        }
        __syncthreads();   // STG ready

        // ---- 4. run-dedup atomicMax (edges sorted by dst in full pass) ----
        {
            int c = tid >> 3;
            int seg = (tid & 7) * 16;
            const float* sp = STG + c * 132 + seg;
            const int* dsc = dsb + p * 128;
            float v[16];
#pragma unroll
            for (int q = 0; q < 4; q++) {
                float4 f = *(const float4*)(sp + q * 4);
                v[q * 4 + 0] = f.x; v[q * 4 + 1] = f.y;
                v[q * 4 + 2] = f.z; v[q * 4 + 3] = f.w;
            }
            int d = dsc[seg];
            float m = v[0];
#pragma unroll
            for (int i = 1; i < 16; i++) {
                int dn = dsc[seg + i];
                if (dn == d) {
                    m = fmaxf(m, v[i]);
                } else {
                    if (d >= 0) atomicMax(&out[d * 64 + c], __float_as_int(m));
                    d = dn;
                    m = v[i];
                }
            }
            if (d >= 0) atomicMax(&out[d * 64 + c], __float_as_int(m));
        }
        __syncthreads();   // ds/ss[p] free for reuse

        // ---- 5. prefetch ds/ss (tile t + 2*stride) into buf p ----
        if (tid < TILE_E) {
            long long tt = (long long)t + 2 * stride;
            long long e = tt * TILE_E + tid;
            int ok = (tt < tile_end) && (e < E);
            dsb[p * 128 + tid] = ok ? DST[e] : -1;
            ssb[p * 128 + tid] = ok ? SRC[e] : 0;
        }
        p ^= 1;
    }
}

// ------------------------------ batchnorm ----------------------------------

__global__ void k_bnstats(int layer, int n) {  // grid 128, block 256
    const int* raw = layer ? g_raw2 : g_raw1;
    int tid = threadIdx.x;
    int c = tid & 63, gq = tid >> 6;
    float s = 0.f, s2 = 0.f;
    for (int r = blockIdx.x * 4 + gq; r < n; r += 512) {
        float v = __int_as_float(raw[r * 64 + c]);
        s += v;
        s2 += v * v;
    }
    __shared__ float sh[256], sh2[256];
    sh[tid] = s;
    sh2[tid] = s2;
    __syncthreads();
    if (gq == 0) {
#pragma unroll
        for (int q = 1; q < 4; q++) {
            s += sh[q * 64 + c];
            s2 += sh2[q * 64 + c];
        }
        g_part[blockIdx.x * 128 + c] = s;
        g_part[blockIdx.x * 128 + 64 + c] = s2;
    }
}

__global__ void k_bnfinal(const float* __restrict__ gamma,
                          const float* __restrict__ beta, int n, int layer) {
    int c = threadIdx.x;
    if (c < 64) {
        float s = 0.f, s2 = 0.f;
        for (int b = 0; b < 128; b++) {
            s += g_part[b * 128 + c];
            s2 += g_part[b * 128 + 64 + c];
        }
        float mean = s / (float)n;
        float var = s2 / (float)n - mean * mean;
        float sc = gamma[c] * rsqrtf(var + 1e-5f);
        g_scale[layer * 64 + c] = sc;
        g_shift[layer * 64 + c] = beta[c] - mean * sc;
    }
}

// ---------------------- pooling + BN2 finalize + h write --------------------

__global__ __launch_bounds__(256) void k_pool(
    const int* __restrict__ batch, int n, int G,
    float* __restrict__ outh, float* __restrict__ outg) {
    int g = blockIdx.x;
    int lo = 0, hi = n;
    while (lo < hi) {
        int mid = (lo + hi) >> 1;
        if (batch[mid] < g) lo = mid + 1; else hi = mid;
    }
    int start = lo;
    hi = n;
    while (lo < hi) {
        int mid = (lo + hi) >> 1;
        if (batch[mid] < g + 1) lo = mid + 1; else hi = mid;
    }
    int end = lo;

    int tid = threadIdx.x;
    int c = tid & 63, gq = tid >> 6;
    float sc = g_scale[64 + c], sh = g_shift[64 + c];
    float s = 0.f, m = __int_as_float(NEG_INF_BITS);
    for (int r = start + gq; r < end; r += 4) {
        float v = __int_as_float(g_raw2[r * 64 + c]) * sc + sh;
        outh[(size_t)r * 64 + c] = v;
        s += v;
        m = fmaxf(m, v);
    }
    __shared__ float shs[256], shm[256];
    shs[tid] = s;
    shm[tid] = m;
    __syncthreads();
    if (gq == 0) {
#pragma unroll
        for (int q = 1; q < 4; q++) {
            s += shs[q * 64 + c];
            m = fmaxf(m, shm[q * 64 + c]);
        }
        int cnt = end - start;
        float mean = s / fmaxf((float)cnt, 1.f);
        float mx = (cnt > 0) ? m : __int_as_float(NEG_INF_BITS);
        outg[g * 128 + c] = mean;
        outg[g * 128 + 64 + c] = mx;
    }
}

// ------------------------------- launch ------------------------------------

extern "C" void kernel_launch(void* const* d_in, const int* in_sizes, int n_in,
                              void* d_out, int out_size) {
    const float* x    = (const float*)d_in[0];
    const int*   ei   = (const int*)d_in[1];
    const int*   batch = (const int*)d_in[2];
    const float* W1a = (const float*)d_in[3];
    const float* b1a = (const float*)d_in[4];
    const float* W1b = (const float*)d_in[5];
    const float* b1b = (const float*)d_in[6];
    const float* g1  = (const float*)d_in[7];
    const float* be1 = (const float*)d_in[8];
    const float* W2a = (const float*)d_in[9];
    const float* b2a = (const float*)d_in[10];
    const float* W2b = (const float*)d_in[11];
    const float* b2b = (const float*)d_in[12];
    const float* g2  = (const float*)d_in[13];
    const float* be2 = (const float*)d_in[14];

    int N = in_sizes[0] / 64;
    int E = in_sizes[1] / 2;
    int G = (out_size - N * 64) / 128;
    const int* src = ei;
    const int* dst = ei + E;

    float* outh = (float*)d_out;
    float* outg = outh + (size_t)N * 64;

    cudaFuncSetAttribute(k_edge_mma,
                         cudaFuncAttributeMaxDynamicSharedMemorySize,
                         SM_EDGE_TOTAL);

    int ntiles = (E + TILE_E - 1) / TILE_E;

    // [0] init raw1 + zero counters
    k_init_raw<<<2048, 256>>>(0, N * 64, N);
    // [1] node linear for layer 1
    k_nodelin<<<(N + 31) / 32, 256>>>(x, 0, W1a, b1a, N);
    // [2] histogram (independent of probe)
    k_hist<<<1024, 256>>>(dst, E);
    // [3] ncu probe: 100 tiles over the RAW edge list (subset-max, neutral)
    k_edge_mma<<<100, 512, SM_EDGE_TOTAL>>>(W1b, b1b, src, dst, 1, 0, 100, E, 0);

    // --- rest of the counting sort ---
    int nch = (N + 1023) / 1024;
    k_scan1<<<nch, 1024>>>(N);
    k_scan2<<<1, 64>>>(nch);
    k_scan3<<<(N + 255) / 256, 256>>>(N);
    k_scatter<<<1024, 256>>>(src, dst, E);

    // --- layer 1 (full pass over sorted edges) ---
    k_edge_mma<<<152, 512, SM_EDGE_TOTAL>>>(W1b, b1b, src, dst, 0, 0, ntiles,
                                            E, 0);
    k_bnstats<<<128, 256>>>(0, N);
    k_bnfinal<<<1, 64>>>(g1, be1, N, 0);

    // --- layer 2 (BN1 folded into the node linear via g_scale/g_shift) ---
    k_nodelin<<<(N + 31) / 32, 256>>>(nullptr, 1, W2a, b2a, N);
    k_init_raw<<<2048, 256>>>(1, N * 64, 0);
    k_edge_mma<<<152, 512, SM_EDGE_TOTAL>>>(W2b, b2b, src, dst, 0, 0, ntiles,
                                            E, 1);
    k_bnstats<<<128, 256>>>(1, N);
    k_bnfinal<<<1, 64>>>(g2, be2, N, 1);

    // --- BN2 finalize + h write + mean/max pooling ---
    k_pool<<<G, 256>>>(batch, N, G, outh, outg);
}

// round 14
// speedup vs baseline: 1.2852x; 1.0076x over previous
#include <cuda_runtime.h>
#include <cuda_fp16.h>
#include <cstdint>

// ---------------------------------------------------------------------------
// GNNEncoder: 2x (EdgeConv -> BatchNorm) + mean/max pooling
//
// Algebra: concat[x_i, x_j-x_i] @ Wa = x_i@(Wtop-Wbot) + x_j@Wbot
//   => per-node A[i], B[j]; per-edge layer-1 is A[dst]+B[src]
// BatchNorm folded into next node GEMM / pooling. Edges counting-sorted by
// dst => run-dedup atomicMax epilogue.
// R14: 2-term f16 split (W = Wh+Wl exact, A rounded once) + occupancy 2:
//      gather register-pipeline dropped (proven null) => ~64 live regs,
//      52 KB SMEM => 2 CTAs/SM overlap each other's serialized phases.
// ---------------------------------------------------------------------------

#define HC 64
#define NMAX 50000
#define EMAX 1600000
#define NEG_INF_BITS ((int)0xFF800000u)

typedef unsigned long long u64;

#define FMA2(d, a, b, c) \
    asm("fma.rn.f32x2 %0, %1, %2, %3;" : "=l"(d) : "l"(a), "l"(b), "l"(c))
#define PACK2(d, v) \
    asm("mov.b64 %0, {%1, %1};" : "=l"(d) : "r"(v))
#define UNPACK2(lo, hi, v) \
    asm("mov.b64 {%0, %1}, %2;" : "=r"(lo), "=r"(hi) : "l"(v))

// fp32-accumulator f16 HMMA
#define MMAF16(c, a0, a1, a2, a3, b0, b1)                                    \
    asm volatile(                                                            \
        "mma.sync.aligned.m16n8k16.row.col.f32.f16.f16.f32 "                 \
        "{%0,%1,%2,%3}, {%4,%5,%6,%7}, {%8,%9}, {%0,%1,%2,%3};"              \
        : "+f"((c)[0]), "+f"((c)[1]), "+f"((c)[2]), "+f"((c)[3])             \
        : "r"(a0), "r"(a1), "r"(a2), "r"(a3), "r"(b0), "r"(b1))

__device__ __forceinline__ uint32_t pack_h2(__half lo, __half hi) {
    return (uint32_t)__half_as_ushort(lo) |
           ((uint32_t)__half_as_ushort(hi) << 16);
}
__device__ __forceinline__ uint32_t hpack(float x0, float x1) {
    return pack_h2(__float2half_rn(x0), __float2half_rn(x1));
}

__device__ int   g_cnt[NMAX];
__device__ int   g_chunk[256];
__device__ int   g_src[EMAX];
__device__ int   g_dst[EMAX];
__device__ float g_A[NMAX * HC];
__device__ float g_B[NMAX * HC];
__device__ int   g_raw1[NMAX * HC];   // float bits, atomicMax as signed int
__device__ int   g_raw2[NMAX * HC];
__device__ float g_part[128 * 2 * HC];
__device__ float g_scale[2 * HC];
__device__ float g_shift[2 * HC];

// ---------------------------- small utilities ------------------------------

__global__ void k_init_raw(int layer, int n, int ncnt) {
    int* raw = layer ? g_raw2 : g_raw1;
    for (int i = blockIdx.x * blockDim.x + threadIdx.x; i < n;
         i += gridDim.x * blockDim.x) {
        raw[i] = NEG_INF_BITS;
        if (i < ncnt) g_cnt[i] = 0;
    }
}

__global__ void k_hist(const int* __restrict__ dst, int E) {
    for (int e = blockIdx.x * blockDim.x + threadIdx.x; e < E;
         e += gridDim.x * blockDim.x)
        atomicAdd(&g_cnt[dst[e]], 1);
}

__global__ void k_scan1(int n) {  // blockDim = 1024
    __shared__ int s[1024];
    int i = blockIdx.x * 1024 + threadIdx.x;
    int v = (i < n) ? g_cnt[i] : 0;
    s[threadIdx.x] = v;
    __syncthreads();
    for (int off = 1; off < 1024; off <<= 1) {
        int t = 0;
        if (threadIdx.x >= off) t = s[threadIdx.x - off];
        __syncthreads();
        s[threadIdx.x] += t;
        __syncthreads();
    }
    if (i < n) g_cnt[i] = s[threadIdx.x] - v;   // exclusive within chunk
    if (threadIdx.x == 1023) g_chunk[blockIdx.x] = s[1023];
}

__global__ void k_scan2(int nch) {  // blockDim = 64, nch <= 64
    __shared__ int s[64];
    int i = threadIdx.x;
    int v = (i < nch) ? g_chunk[i] : 0;
    s[i] = v;
    __syncthreads();
    for (int off = 1; off < 64; off <<= 1) {
        int t = (i >= off) ? s[i - off] : 0;
        __syncthreads();
        s[i] += t;
        __syncthreads();
    }
    if (i < nch) g_chunk[i] = s[i] - v;   // exclusive
}

__global__ void k_scan3(int n) {
    int i = blockIdx.x * blockDim.x + threadIdx.x;
    if (i < n) g_cnt[i] += g_chunk[i >> 10];
}

__global__ void k_scatter(const int* __restrict__ src,
                          const int* __restrict__ dst, int E) {
    for (int e = blockIdx.x * blockDim.x + threadIdx.x; e < E;
         e += gridDim.x * blockDim.x) {
        int d = dst[e];
        int p = atomicAdd(&g_cnt[d], 1);
        g_src[p] = src[e];
        g_dst[p] = d;
    }
}

// ------------------------- per-node linear (A, B) ---------------------------

__global__ __launch_bounds__(256) void k_nodelin(
    const float* __restrict__ xin, int use_raw,
    const float* __restrict__ Wa,  // [128,64] row-major
    const float* __restrict__ ba, int n) {
    __shared__ float Ws[128 * 64];
    __shared__ float xs[32 * 65];
    int tid = threadIdx.x;
    for (int i = tid; i < 128 * 64; i += 256) Ws[i] = Wa[i];

    int row0 = blockIdx.x * 32;
    for (int i = tid; i < 32 * 64; i += 256) {
        int r = i >> 6, k = i & 63;
        int row = row0 + r;
        float v = 0.f;
        if (row < n) {
            if (use_raw)
                v = __int_as_float(g_raw1[row * 64 + k]) * g_scale[k] + g_shift[k];
            else
                v = xin[row * 64 + k];
        }
        xs[r * 65 + k] = v;
    }
    __syncthreads();

    int r = tid & 31, cg = tid >> 5;
    int c0 = cg * 8;
    u64 a2[4], b2[4];
#pragma unroll
    for (int j = 0; j < 4; j++) { a2[j] = 0ull; b2[j] = 0ull; }

#pragma unroll 8
    for (int k = 0; k < 64; k++) {
        float xv = xs[r * 65 + k];
        u64 xp;
        PACK2(xp, __float_as_uint(xv));
        ulonglong2 t0 = *(const ulonglong2*)&Ws[k * 64 + c0];
        ulonglong2 t1 = *(const ulonglong2*)&Ws[k * 64 + c0 + 4];
        ulonglong2 q0 = *(const ulonglong2*)&Ws[(64 + k) * 64 + c0];
        ulonglong2 q1 = *(const ulonglong2*)&Ws[(64 + k) * 64 + c0 + 4];
        FMA2(a2[0], xp, t0.x, a2[0]);
        FMA2(a2[1], xp, t0.y, a2[1]);
        FMA2(a2[2], xp, t1.x, a2[2]);
        FMA2(a2[3], xp, t1.y, a2[3]);
        FMA2(b2[0], xp, q0.x, b2[0]);
        FMA2(b2[1], xp, q0.y, b2[1]);
        FMA2(b2[2], xp, q1.x, b2[2]);
        FMA2(b2[3], xp, q1.y, b2[3]);
    }
    int row = row0 + r;
    if (row < n) {
        float a[8], b[8];
#pragma unroll
        for (int j = 0; j < 4; j++) {
            unsigned int lo, hi;
            UNPACK2(lo, hi, a2[j]);
            a[2 * j] = __uint_as_float(lo);
            a[2 * j + 1] = __uint_as_float(hi);
            UNPACK2(lo, hi, b2[j]);
            b[2 * j] = __uint_as_float(lo);
            b[2 * j + 1] = __uint_as_float(hi);
        }
#pragma unroll
        for (int j = 0; j < 8; j++) {
            float bb = ba[c0 + j];
            g_A[row * 64 + c0 + j] = a[j] - b[j] + bb;
            g_B[row * 64 + c0 + j] = b[j];
        }
    }
}

// --------- edge kernel (f16 2-term, W split exact, occupancy 2) -------------
// k-order permuted identically in A and W tiles (dot products invariant):
// orig k-pair word w stored at pos = (w&3)*8 + (w>>2); MMA thread fragments
// contiguous (LDS.64). 16 warps: warp (eg 0..7, nh 0..1) = 16 edges x 32 cols.
// No gather register pipeline (proven null) => fits 64 regs => 2 CTAs/SM.

#define TILE_E 128
#define AROW 34                             // u32 stride per edge row (pad)
// dynamic smem (bytes)
#define SMO_DS   0                          // int [128]
#define SMO_SS   512                        // int [128]
#define SMO_AH   1024                       // [128][34] u32 = 17408 B
#define SMO_STG  18432                      // [64][132] f32 = 33792 B
#define SMO_WTH  18432                      // init-only alias, [64][34] u32
#define SMO_WTL  27136                      // init-only alias
#define SM_EDGE_TOTAL 52224

__global__ __launch_bounds__(512, 2) void k_edge_mma(
    const float* __restrict__ Wb,   // [64k][64n]
    const float* __restrict__ bb,   // [64]
    const int* __restrict__ psrc, const int* __restrict__ pdst, int use_p,
    int tile_begin, int tile_end, int E, int layer) {
    extern __shared__ char sm[];
    int* ds = (int*)(sm + SMO_DS);
    int* ss = (int*)(sm + SMO_SS);
    uint32_t* AH = (uint32_t*)(sm + SMO_AH);
    float* STG = (float*)(sm + SMO_STG);
    uint32_t* WTH = (uint32_t*)(sm + SMO_WTH);
    uint32_t* WTL = (uint32_t*)(sm + SMO_WTL);

    const int* SRC = use_p ? psrc : g_src;
    const int* DST = use_p ? pdst : g_dst;

    int* out = layer ? g_raw2 : g_raw1;
    int tid = threadIdx.x;
    int wid = tid >> 5, lid = tid & 31;
    int gid = lid >> 2, tig = lid & 3;
    int eg = wid & 7, nh = wid >> 3;

    // ---- W exact split -> SMEM in permuted-k fragment layout ----
    for (int i = tid; i < 64 * 32; i += 512) {
        int n = i >> 5, wp = i & 31;           // orig k-pair index wp
        float w0 = Wb[(2 * wp) * 64 + n];
        float w1 = Wb[(2 * wp + 1) * 64 + n];
        __half h0 = __float2half_rn(w0);
        __half h1 = __float2half_rn(w1);
        __half l0 = __float2half_rn(w0 - __half2float(h0));
        __half l1 = __float2half_rn(w1 - __half2float(h1));
        int pos = (wp & 3) * 8 + (wp >> 2);
        WTH[n * AROW + pos] = pack_h2(h0, h1);
        WTL[n * AROW + pos] = pack_h2(l0, l1);
    }
    __syncthreads();

    // ---- W fragments to registers (held for whole kernel) ----
    uint32_t wh0[4][4], wh1[4][4], wl0[4][4], wl1[4][4];
#pragma unroll
    for (int kt = 0; kt < 4; kt++)
#pragma unroll
        for (int nt = 0; nt < 4; nt++) {
            int n = nh * 32 + nt * 8 + gid;
            uint2 wh = *(const uint2*)&WTH[n * AROW + tig * 8 + kt * 2];
            uint2 wl = *(const uint2*)&WTL[n * AROW + tig * 8 + kt * 2];
            wh0[kt][nt] = wh.x;
            wh1[kt][nt] = wh.y;
            wl0[kt][nt] = wl.x;
            wl1[kt][nt] = wl.y;
        }
    float bias[4][2];
#pragma unroll
    for (int nt = 0; nt < 4; nt++) {
        int c0 = nh * 32 + nt * 8 + tig * 2;
        bias[nt][0] = bb[c0];
        bias[nt][1] = bb[c0 + 1];
    }
    __syncthreads();   // done with WTH/WTL region (aliases staging)

    int stride = gridDim.x;
    int ge = tid >> 2, gp = tid & 3;   // gather: 4 threads/edge, 16 k each

    for (int t = tile_begin + (int)blockIdx.x; t < tile_end; t += stride) {
        // ---- 0. tile indices ----
        if (tid < TILE_E) {
            long long e = (long long)t * TILE_E + tid;
            ds[tid] = (e < E) ? DST[e] : -1;
            ss[tid] = (e < E) ? SRC[e] : 0;
        }
        __syncthreads();

        // ---- 1. gather + relu + f16 round -> AH (permuted-k layout) ----
        {
            int d = ds[ge], s = ss[ge];
            uint32_t hw[8];
            if (d >= 0) {
                const float4* ap =
                    (const float4*)&g_A[(size_t)d * 64 + gp * 16];
                const float4* bp =
                    (const float4*)&g_B[(size_t)s * 64 + gp * 16];
#pragma unroll
                for (int q = 0; q < 4; q++) {
                    float4 av = ap[q], bv = bp[q];
                    hw[2 * q] = hpack(fmaxf(av.x + bv.x, 0.f),
                                      fmaxf(av.y + bv.y, 0.f));
                    hw[2 * q + 1] = hpack(fmaxf(av.z + bv.z, 0.f),
                                          fmaxf(av.w + bv.w, 0.f));
                }
            } else {
#pragma unroll
                for (int j = 0; j < 8; j++) hw[j] = 0u;
            }
            uint32_t* ah = AH + ge * AROW + gp * 2;
#pragma unroll
            for (int jj = 0; jj < 4; jj++)
                *(uint2*)(ah + jj * 8) = make_uint2(hw[jj], hw[jj + 4]);
        }
        __syncthreads();

        // ---- 2. MMA: 2 terms (a*Wh + a*Wl), fp32 accum ----
        float acc[4][4];
#pragma unroll
        for (int nt = 0; nt < 4; nt++)
#pragma unroll
            for (int j = 0; j < 4; j++) acc[nt][j] = 0.f;

        int erow = eg * 16 + gid;
#pragma unroll
        for (int kt = 0; kt < 4; kt++) {
            int fo = tig * 8 + kt * 2;
            uint2 a02 = *(const uint2*)&AH[erow * AROW + fo];
            uint2 a13 = *(const uint2*)&AH[(erow + 8) * AROW + fo];
#pragma unroll
            for (int nt = 0; nt < 4; nt++) {
                MMAF16(acc[nt], a02.x, a13.x, a02.y, a13.y,
                       wh0[kt][nt], wh1[kt][nt]);
                MMAF16(acc[nt], a02.x, a13.x, a02.y, a13.y,
                       wl0[kt][nt], wl1[kt][nt]);
            }
        }

        // ---- 3. bias + relu -> staging [col][edge] stride 132 ----
#pragma unroll
        for (int nt = 0; nt < 4; nt++) {
            int c0 = nh * 32 + nt * 8 + tig * 2;
            STG[c0 * 132 + erow] = fmaxf(acc[nt][0] + bias[nt][0], 0.f);
            STG[(c0 + 1) * 132 + erow] = fmaxf(acc[nt][1] + bias[nt][1], 0.f);
            STG[c0 * 132 + erow + 8] = fmaxf(acc[nt][2] + bias[nt][0], 0.f);
            STG[(c0 + 1) * 132 + erow + 8] = fmaxf(acc[nt][3] + bias[nt][1], 0.f);
        }
        __syncthreads();   // STG ready

        // ---- 4. run-dedup atomicMax (edges sorted by dst in full pass) ----
        {
            int c = tid >> 3;
            int seg = (tid & 7) * 16;
            const float* sp = STG + c * 132 + seg;
            const int* dsc = ds + seg;
            float v[16];
#pragma unroll
            for (int q = 0; q < 4; q++) {
                float4 f = *(const float4*)(sp + q * 4);
                v[q * 4 + 0] = f.x; v[q * 4 + 1] = f.y;
                v[q * 4 + 2] = f.z; v[q * 4 + 3] = f.w;
            }
            int d = dsc[0];
            float m = v[0];
#pragma unroll
            for (int i = 1; i < 16; i++) {
                int dn = dsc[i];
                if (dn == d) {
                    m = fmaxf(m, v[i]);
                } else {
                    if (d >= 0) atomicMax(&out[d * 64 + c], __float_as_int(m));
                    d = dn;
                    m = v[i];
                }
            }
            if (d >= 0) atomicMax(&out[d * 64 + c], __float_as_int(m));
        }
        __syncthreads();   // ds/ss + AH + STG free for next tile
    }
}

// ------------------------------ batchnorm ----------------------------------

__global__ void k_bnstats(int layer, int n) {  // grid 128, block 256
    const int* raw = layer ? g_raw2 : g_raw1;
    int tid = threadIdx.x;
    int c = tid & 63, gq = tid >> 6;
    float s = 0.f, s2 = 0.f;
    for (int r = blockIdx.x * 4 + gq; r < n; r += 512) {
        float v = __int_as_float(raw[r * 64 + c]);
        s += v;
        s2 += v * v;
    }
    __shared__ float sh[256], sh2[256];
    sh[tid] = s;
    sh2[tid] = s2;
    __syncthreads();
    if (gq == 0) {
#pragma unroll
        for (int q = 1; q < 4; q++) {
            s += sh[q * 64 + c];
            s2 += sh2[q * 64 + c];
        }
        g_part[blockIdx.x * 128 + c] = s;
        g_part[blockIdx.x * 128 + 64 + c] = s2;
    }
}

__global__ void k_bnfinal(const float* __restrict__ gamma,
                          const float* __restrict__ beta, int n, int layer) {
    int c = threadIdx.x;
    if (c < 64) {
        float s = 0.f, s2 = 0.f;
        for (int b = 0; b < 128; b++) {
            s += g_part[b * 128 + c];
            s2 += g_part[b * 128 + 64 + c];
        }
        float mean = s / (float)n;
        float var = s2 / (float)n - mean * mean;
        float sc = gamma[c] * rsqrtf(var + 1e-5f);
        g_scale[layer * 64 + c] = sc;
        g_shift[layer * 64 + c] = beta[c] - mean * sc;
    }
}

// ---------------------- pooling + BN2 finalize + h write --------------------

__global__ __launch_bounds__(256) void k_pool(
    const int* __restrict__ batch, int n, int G,
    float* __restrict__ outh, float* __restrict__ outg) {
    int g = blockIdx.x;
    int lo = 0, hi = n;
    while (lo < hi) {
        int mid = (lo + hi) >> 1;
        if (batch[mid] < g) lo = mid + 1; else hi = mid;
    }
    int start = lo;
    hi = n;
    while (lo < hi) {
        int mid = (lo + hi) >> 1;
        if (batch[mid] < g + 1) lo = mid + 1; else hi = mid;
    }
    int end = lo;

    int tid = threadIdx.x;
    int c = tid & 63, gq = tid >> 6;
    float sc = g_scale[64 + c], sh = g_shift[64 + c];
    float s = 0.f, m = __int_as_float(NEG_INF_BITS);
    for (int r = start + gq; r < end; r += 4) {
        float v = __int_as_float(g_raw2[r * 64 + c]) * sc + sh;
        outh[(size_t)r * 64 + c] = v;
        s += v;
        m = fmaxf(m, v);
    }
    __shared__ float shs[256], shm[256];
    shs[tid] = s;
    shm[tid] = m;
    __syncthreads();
    if (gq == 0) {
#pragma unroll
        for (int q = 1; q < 4; q++) {
            s += shs[q * 64 + c];
            m = fmaxf(m, shm[q * 64 + c]);
        }
        int cnt = end - start;
        float mean = s / fmaxf((float)cnt, 1.f);
        float mx = (cnt > 0) ? m : __int_as_float(NEG_INF_BITS);
        outg[g * 128 + c] = mean;
        outg[g * 128 + 64 + c] = mx;
    }
}

// ------------------------------- launch ------------------------------------

extern "C" void kernel_launch(void* const* d_in, const int* in_sizes, int n_in,
                              void* d_out, int out_size) {
    const float* x    = (const float*)d_in[0];
    const int*   ei   = (const int*)d_in[1];
    const int*   batch = (const int*)d_in[2];
    const float* W1a = (const float*)d_in[3];
    const float* b1a = (const float*)d_in[4];
    const float* W1b = (const float*)d_in[5];
    const float* b1b = (const float*)d_in[6];
    const float* g1  = (const float*)d_in[7];
    const float* be1 = (const float*)d_in[8];
    const float* W2a = (const float*)d_in[9];
    const float* b2a = (const float*)d_in[10];
    const float* W2b = (const float*)d_in[11];
    const float* b2b = (const float*)d_in[12];
    const float* g2  = (const float*)d_in[13];
    const float* be2 = (const float*)d_in[14];

    int N = in_sizes[0] / 64;
    int E = in_sizes[1] / 2;
    int G = (out_size - N * 64) / 128;
    const int* src = ei;
    const int* dst = ei + E;

    float* outh = (float*)d_out;
    float* outg = outh + (size_t)N * 64;

    cudaFuncSetAttribute(k_edge_mma,
                         cudaFuncAttributeMaxDynamicSharedMemorySize,
                         SM_EDGE_TOTAL);

    int ntiles = (E + TILE_E - 1) / TILE_E;
    int egrid = 304;    // 2 CTAs/SM

    // [0] init raw1 + zero counters
    k_init_raw<<<2048, 256>>>(0, N * 64, N);
    // [1] node linear for layer 1
    k_nodelin<<<(N + 31) / 32, 256>>>(x, 0, W1a, b1a, N);
    // [2] histogram (independent of probe)
    k_hist<<<1024, 256>>>(dst, E);
    // [3] ncu probe: 96 tiles, 8 per CTA => steady-state metrics
    k_edge_mma<<<12, 512, SM_EDGE_TOTAL>>>(W1b, b1b, src, dst, 1, 0, 96, E, 0);

    // --- rest of the counting sort ---
    int nch = (N + 1023) / 1024;
    k_scan1<<<nch, 1024>>>(N);
    k_scan2<<<1, 64>>>(nch);
    k_scan3<<<(N + 255) / 256, 256>>>(N);
    k_scatter<<<1024, 256>>>(src, dst, E);

    // --- layer 1 (full pass over sorted edges) ---
    k_edge_mma<<<egrid, 512, SM_EDGE_TOTAL>>>(W1b, b1b, src, dst, 0, 0, ntiles,
                                              E, 0);
    k_bnstats<<<128, 256>>>(0, N);
    k_bnfinal<<<1, 64>>>(g1, be1, N, 0);

    // --- layer 2 (BN1 folded into the node linear via g_scale/g_shift) ---
    k_nodelin<<<(N + 31) / 32, 256>>>(nullptr, 1, W2a, b2a, N);
    k_init_raw<<<2048, 256>>>(1, N * 64, 0);
    k_edge_mma<<<egrid, 512, SM_EDGE_TOTAL>>>(W2b, b2b, src, dst, 0, 0, ntiles,
                                              E, 1);
    k_bnstats<<<128, 256>>>(1, N);
    k_bnfinal<<<1, 64>>>(g2, be2, N, 1);

    // --- BN2 finalize + h write + mean/max pooling ---
    k_pool<<<G, 256>>>(batch, N, G, outh, outg);
}

// round 15
// speedup vs baseline: 1.3574x; 1.0561x over previous
#include <cuda_runtime.h>
#include <cuda_fp16.h>
#include <cstdint>

// ---------------------------------------------------------------------------
// GNNEncoder: 2x (EdgeConv -> BatchNorm) + mean/max pooling
//
// Algebra: concat[x_i, x_j-x_i] @ Wa = x_i@(Wtop-Wbot) + x_j@Wbot
//   => per-node A[i], B[j]; per-edge layer-1 is A[dst]+B[src]
// BatchNorm folded into next node GEMM / pooling. Edges counting-sorted by
// dst => run-dedup atomicMax epilogue.
// R15: occupancy-2 2-term f16 edge kernel (R14) +
//      cheap probe (304 CTAs x 1 tile) + int2-packed sorted edge list
//      (halves scatter transactions, coalesced tile index loads).
// ---------------------------------------------------------------------------

#define HC 64
#define NMAX 50000
#define EMAX 1600000
#define NEG_INF_BITS ((int)0xFF800000u)

typedef unsigned long long u64;

#define FMA2(d, a, b, c) \
    asm("fma.rn.f32x2 %0, %1, %2, %3;" : "=l"(d) : "l"(a), "l"(b), "l"(c))
#define PACK2(d, v) \
    asm("mov.b64 %0, {%1, %1};" : "=l"(d) : "r"(v))
#define UNPACK2(lo, hi, v) \
    asm("mov.b64 {%0, %1}, %2;" : "=r"(lo), "=r"(hi) : "l"(v))

// fp32-accumulator f16 HMMA
#define MMAF16(c, a0, a1, a2, a3, b0, b1)                                    \
    asm volatile(                                                            \
        "mma.sync.aligned.m16n8k16.row.col.f32.f16.f16.f32 "                 \
        "{%0,%1,%2,%3}, {%4,%5,%6,%7}, {%8,%9}, {%0,%1,%2,%3};"              \
        : "+f"((c)[0]), "+f"((c)[1]), "+f"((c)[2]), "+f"((c)[3])             \
        : "r"(a0), "r"(a1), "r"(a2), "r"(a3), "r"(b0), "r"(b1))

__device__ __forceinline__ uint32_t pack_h2(__half lo, __half hi) {
    return (uint32_t)__half_as_ushort(lo) |
           ((uint32_t)__half_as_ushort(hi) << 16);
}
__device__ __forceinline__ uint32_t hpack(float x0, float x1) {
    return pack_h2(__float2half_rn(x0), __float2half_rn(x1));
}

__device__ int   g_cnt[NMAX];
__device__ int   g_chunk[256];
__device__ int2  g_edge[EMAX];        // (src, dst) sorted by dst
__device__ float g_A[NMAX * HC];
__device__ float g_B[NMAX * HC];
__device__ int   g_raw1[NMAX * HC];   // float bits, atomicMax as signed int
__device__ int   g_raw2[NMAX * HC];
__device__ float g_part[128 * 2 * HC];
__device__ float g_scale[2 * HC];
__device__ float g_shift[2 * HC];

// ---------------------------- small utilities ------------------------------

__global__ void k_init_raw(int layer, int n, int ncnt) {
    int* raw = layer ? g_raw2 : g_raw1;
    for (int i = blockIdx.x * blockDim.x + threadIdx.x; i < n;
         i += gridDim.x * blockDim.x) {
        raw[i] = NEG_INF_BITS;
        if (i < ncnt) g_cnt[i] = 0;
    }
}

__global__ void k_hist(const int* __restrict__ dst, int E) {
    for (int e = blockIdx.x * blockDim.x + threadIdx.x; e < E;
         e += gridDim.x * blockDim.x)
        atomicAdd(&g_cnt[dst[e]], 1);
}

__global__ void k_scan1(int n) {  // blockDim = 1024
    __shared__ int s[1024];
    int i = blockIdx.x * 1024 + threadIdx.x;
    int v = (i < n) ? g_cnt[i] : 0;
    s[threadIdx.x] = v;
    __syncthreads();
    for (int off = 1; off < 1024; off <<= 1) {
        int t = 0;
        if (threadIdx.x >= off) t = s[threadIdx.x - off];
        __syncthreads();
        s[threadIdx.x] += t;
        __syncthreads();
    }
    if (i < n) g_cnt[i] = s[threadIdx.x] - v;   // exclusive within chunk
    if (threadIdx.x == 1023) g_chunk[blockIdx.x] = s[1023];
}

__global__ void k_scan2(int nch) {  // blockDim = 64, nch <= 64
    __shared__ int s[64];
    int i = threadIdx.x;
    int v = (i < nch) ? g_chunk[i] : 0;
    s[i] = v;
    __syncthreads();
    for (int off = 1; off < 64; off <<= 1) {
        int t = (i >= off) ? s[i - off] : 0;
        __syncthreads();
        s[i] += t;
        __syncthreads();
    }
    if (i < nch) g_chunk[i] = s[i] - v;   // exclusive
}

__global__ void k_scan3(int n) {
    int i = blockIdx.x * blockDim.x + threadIdx.x;
    if (i < n) g_cnt[i] += g_chunk[i >> 10];
}

__global__ void k_scatter(const int* __restrict__ src,
                          const int* __restrict__ dst, int E) {
    for (int e = blockIdx.x * blockDim.x + threadIdx.x; e < E;
         e += gridDim.x * blockDim.x) {
        int d = dst[e];
        int p = atomicAdd(&g_cnt[d], 1);
        g_edge[p] = make_int2(src[e], d);
    }
}

// ------------------------- per-node linear (A, B) ---------------------------

__global__ __launch_bounds__(256) void k_nodelin(
    const float* __restrict__ xin, int use_raw,
    const float* __restrict__ Wa,  // [128,64] row-major
    const float* __restrict__ ba, int n) {
    __shared__ float Ws[128 * 64];
    __shared__ float xs[32 * 65];
    int tid = threadIdx.x;
    for (int i = tid; i < 128 * 64; i += 256) Ws[i] = Wa[i];

    int row0 = blockIdx.x * 32;
    for (int i = tid; i < 32 * 64; i += 256) {
        int r = i >> 6, k = i & 63;
        int row = row0 + r;
        float v = 0.f;
        if (row < n) {
            if (use_raw)
                v = __int_as_float(g_raw1[row * 64 + k]) * g_scale[k] + g_shift[k];
            else
                v = xin[row * 64 + k];
        }
        xs[r * 65 + k] = v;
    }
    __syncthreads();

    int r = tid & 31, cg = tid >> 5;
    int c0 = cg * 8;
    u64 a2[4], b2[4];
#pragma unroll
    for (int j = 0; j < 4; j++) { a2[j] = 0ull; b2[j] = 0ull; }

#pragma unroll 8
    for (int k = 0; k < 64; k++) {
        float xv = xs[r * 65 + k];
        u64 xp;
        PACK2(xp, __float_as_uint(xv));
        ulonglong2 t0 = *(const ulonglong2*)&Ws[k * 64 + c0];
        ulonglong2 t1 = *(const ulonglong2*)&Ws[k * 64 + c0 + 4];
        ulonglong2 q0 = *(const ulonglong2*)&Ws[(64 + k) * 64 + c0];
        ulonglong2 q1 = *(const ulonglong2*)&Ws[(64 + k) * 64 + c0 + 4];
        FMA2(a2[0], xp, t0.x, a2[0]);
        FMA2(a2[1], xp, t0.y, a2[1]);
        FMA2(a2[2], xp, t1.x, a2[2]);
        FMA2(a2[3], xp, t1.y, a2[3]);
        FMA2(b2[0], xp, q0.x, b2[0]);
        FMA2(b2[1], xp, q0.y, b2[1]);
        FMA2(b2[2], xp, q1.x, b2[2]);
        FMA2(b2[3], xp, q1.y, b2[3]);
    }
    int row = row0 + r;
    if (row < n) {
        float a[8], b[8];
#pragma unroll
        for (int j = 0; j < 4; j++) {
            unsigned int lo, hi;
            UNPACK2(lo, hi, a2[j]);
            a[2 * j] = __uint_as_float(lo);
            a[2 * j + 1] = __uint_as_float(hi);
            UNPACK2(lo, hi, b2[j]);
            b[2 * j] = __uint_as_float(lo);
            b[2 * j + 1] = __uint_as_float(hi);
        }
#pragma unroll
        for (int j = 0; j < 8; j++) {
            float bb = ba[c0 + j];
            g_A[row * 64 + c0 + j] = a[j] - b[j] + bb;
            g_B[row * 64 + c0 + j] = b[j];
        }
    }
}

// --------- edge kernel (f16 2-term, W split exact, occupancy 2) -------------
// k-order permuted identically in A and W tiles (dot products invariant):
// orig k-pair word w stored at pos = (w&3)*8 + (w>>2); MMA thread fragments
// contiguous (LDS.64). 16 warps: warp (eg 0..7, nh 0..1) = 16 edges x 32 cols.

#define TILE_E 128
#define AROW 34                             // u32 stride per edge row (pad)
// dynamic smem (bytes)
#define SMO_DS   0                          // int [128]
#define SMO_SS   512                        // int [128]
#define SMO_AH   1024                       // [128][34] u32 = 17408 B
#define SMO_STG  18432                      // [64][132] f32 = 33792 B
#define SMO_WTH  18432                      // init-only alias, [64][34] u32
#define SMO_WTL  27136                      // init-only alias
#define SM_EDGE_TOTAL 52224

__global__ __launch_bounds__(512, 2) void k_edge_mma(
    const float* __restrict__ Wb,   // [64k][64n]
    const float* __restrict__ bb,   // [64]
    const int* __restrict__ psrc, const int* __restrict__ pdst, int use_p,
    int tile_begin, int tile_end, int E, int layer) {
    extern __shared__ char sm[];
    int* ds = (int*)(sm + SMO_DS);
    int* ss = (int*)(sm + SMO_SS);
    uint32_t* AH = (uint32_t*)(sm + SMO_AH);
    float* STG = (float*)(sm + SMO_STG);
    uint32_t* WTH = (uint32_t*)(sm + SMO_WTH);
    uint32_t* WTL = (uint32_t*)(sm + SMO_WTL);

    int* out = layer ? g_raw2 : g_raw1;
    int tid = threadIdx.x;
    int wid = tid >> 5, lid = tid & 31;
    int gid = lid >> 2, tig = lid & 3;
    int eg = wid & 7, nh = wid >> 3;

    // ---- W exact split -> SMEM in permuted-k fragment layout ----
    for (int i = tid; i < 64 * 32; i += 512) {
        int n = i >> 5, wp = i & 31;           // orig k-pair index wp
        float w0 = Wb[(2 * wp) * 64 + n];
        float w1 = Wb[(2 * wp + 1) * 64 + n];
        __half h0 = __float2half_rn(w0);
        __half h1 = __float2half_rn(w1);
        __half l0 = __float2half_rn(w0 - __half2float(h0));
        __half l1 = __float2half_rn(w1 - __half2float(h1));
        int pos = (wp & 3) * 8 + (wp >> 2);
        WTH[n * AROW + pos] = pack_h2(h0, h1);
        WTL[n * AROW + pos] = pack_h2(l0, l1);
    }
    __syncthreads();

    // ---- W fragments to registers (held for whole kernel) ----
    uint32_t wh0[4][4], wh1[4][4], wl0[4][4], wl1[4][4];
#pragma unroll
    for (int kt = 0; kt < 4; kt++)
#pragma unroll
        for (int nt = 0; nt < 4; nt++) {
            int n = nh * 32 + nt * 8 + gid;
            uint2 wh = *(const uint2*)&WTH[n * AROW + tig * 8 + kt * 2];
            uint2 wl = *(const uint2*)&WTL[n * AROW + tig * 8 + kt * 2];
            wh0[kt][nt] = wh.x;
            wh1[kt][nt] = wh.y;
            wl0[kt][nt] = wl.x;
            wl1[kt][nt] = wl.y;
        }
    float bias[4][2];
#pragma unroll
    for (int nt = 0; nt < 4; nt++) {
        int c0 = nh * 32 + nt * 8 + tig * 2;
        bias[nt][0] = bb[c0];
        bias[nt][1] = bb[c0 + 1];
    }
    __syncthreads();   // done with WTH/WTL region (aliases staging)

    int stride = gridDim.x;
    int ge = tid >> 2, gp = tid & 3;   // gather: 4 threads/edge, 16 k each

    for (int t = tile_begin + (int)blockIdx.x; t < tile_end; t += stride) {
        // ---- 0. tile indices ----
        if (tid < TILE_E) {
            long long e = (long long)t * TILE_E + tid;
            if (use_p) {
                ds[tid] = (e < E) ? pdst[e] : -1;
                ss[tid] = (e < E) ? psrc[e] : 0;
            } else if (e < E) {
                int2 v = g_edge[e];
                ds[tid] = v.y;
                ss[tid] = v.x;
            } else {
                ds[tid] = -1;
                ss[tid] = 0;
            }
        }
        __syncthreads();

        // ---- 1. gather + relu + f16 round -> AH (permuted-k layout) ----
        {
            int d = ds[ge], s = ss[ge];
            uint32_t hw[8];
            if (d >= 0) {
                const float4* ap =
                    (const float4*)&g_A[(size_t)d * 64 + gp * 16];
                const float4* bp =
                    (const float4*)&g_B[(size_t)s * 64 + gp * 16];
#pragma unroll
                for (int q = 0; q < 4; q++) {
                    float4 av = ap[q], bv = bp[q];
                    hw[2 * q] = hpack(fmaxf(av.x + bv.x, 0.f),
                                      fmaxf(av.y + bv.y, 0.f));
                    hw[2 * q + 1] = hpack(fmaxf(av.z + bv.z, 0.f),
                                          fmaxf(av.w + bv.w, 0.f));
                }
            } else {
#pragma unroll
                for (int j = 0; j < 8; j++) hw[j] = 0u;
            }
            uint32_t* ah = AH + ge * AROW + gp * 2;
#pragma unroll
            for (int jj = 0; jj < 4; jj++)
                *(uint2*)(ah + jj * 8) = make_uint2(hw[jj], hw[jj + 4]);
        }
        __syncthreads();

        // ---- 2. MMA: 2 terms (a*Wh + a*Wl), fp32 accum ----
        float acc[4][4];
#pragma unroll
        for (int nt = 0; nt < 4; nt++)
#pragma unroll
            for (int j = 0; j < 4; j++) acc[nt][j] = 0.f;

        int erow = eg * 16 + gid;
#pragma unroll
        for (int kt = 0; kt < 4; kt++) {
            int fo = tig * 8 + kt * 2;
            uint2 a02 = *(const uint2*)&AH[erow * AROW + fo];
            uint2 a13 = *(const uint2*)&AH[(erow + 8) * AROW + fo];
#pragma unroll
            for (int nt = 0; nt < 4; nt++) {
                MMAF16(acc[nt], a02.x, a13.x, a02.y, a13.y,
                       wh0[kt][nt], wh1[kt][nt]);
                MMAF16(acc[nt], a02.x, a13.x, a02.y, a13.y,
                       wl0[kt][nt], wl1[kt][nt]);
            }
        }

        // ---- 3. bias + relu -> staging [col][edge] stride 132 ----
#pragma unroll
        for (int nt = 0; nt < 4; nt++) {
            int c0 = nh * 32 + nt * 8 + tig * 2;
            STG[c0 * 132 + erow] = fmaxf(acc[nt][0] + bias[nt][0], 0.f);
            STG[(c0 + 1) * 132 + erow] = fmaxf(acc[nt][1] + bias[nt][1], 0.f);
            STG[c0 * 132 + erow + 8] = fmaxf(acc[nt][2] + bias[nt][0], 0.f);
            STG[(c0 + 1) * 132 + erow + 8] = fmaxf(acc[nt][3] + bias[nt][1], 0.f);
        }
        __syncthreads();   // STG ready

        // ---- 4. run-dedup atomicMax (edges sorted by dst in full pass) ----
        {
            int c = tid >> 3;
            int seg = (tid & 7) * 16;
            const float* sp = STG + c * 132 + seg;
            const int* dsc = ds + seg;
            float v[16];
#pragma unroll
            for (int q = 0; q < 4; q++) {
                float4 f = *(const float4*)(sp + q * 4);
                v[q * 4 + 0] = f.x; v[q * 4 + 1] = f.y;
                v[q * 4 + 2] = f.z; v[q * 4 + 3] = f.w;
            }
            int d = dsc[0];
            float m = v[0];
#pragma unroll
            for (int i = 1; i < 16; i++) {
                int dn = dsc[i];
                if (dn == d) {
                    m = fmaxf(m, v[i]);
                } else {
                    if (d >= 0) atomicMax(&out[d * 64 + c], __float_as_int(m));
                    d = dn;
                    m = v[i];
                }
            }
            if (d >= 0) atomicMax(&out[d * 64 + c], __float_as_int(m));
        }
        __syncthreads();   // ds/ss + AH + STG free for next tile
    }
}

// ------------------------------ batchnorm ----------------------------------

__global__ void k_bnstats(int layer, int n) {  // grid 128, block 256
    const int* raw = layer ? g_raw2 : g_raw1;
    int tid = threadIdx.x;
    int c = tid & 63, gq = tid >> 6;
    float s = 0.f, s2 = 0.f;
    for (int r = blockIdx.x * 4 + gq; r < n; r += 512) {
        float v = __int_as_float(raw[r * 64 + c]);
        s += v;
        s2 += v * v;
    }
    __shared__ float sh[256], sh2[256];
    sh[tid] = s;
    sh2[tid] = s2;
    __syncthreads();
    if (gq == 0) {
#pragma unroll
        for (int q = 1; q < 4; q++) {
            s += sh[q * 64 + c];
            s2 += sh2[q * 64 + c];
        }
        g_part[blockIdx.x * 128 + c] = s;
        g_part[blockIdx.x * 128 + 64 + c] = s2;
    }
}

__global__ void k_bnfinal(const float* __restrict__ gamma,
                          const float* __restrict__ beta, int n, int layer) {
    int c = threadIdx.x;
    if (c < 64) {
        float s = 0.f, s2 = 0.f;
        for (int b = 0; b < 128; b++) {
            s += g_part[b * 128 + c];
            s2 += g_part[b * 128 + 64 + c];
        }
        float mean = s / (float)n;
        float var = s2 / (float)n - mean * mean;
        float sc = gamma[c] * rsqrtf(var + 1e-5f);
        g_scale[layer * 64 + c] = sc;
        g_shift[layer * 64 + c] = beta[c] - mean * sc;
    }
}

// ---------------------- pooling + BN2 finalize + h write --------------------

__global__ __launch_bounds__(256) void k_pool(
    const int* __restrict__ batch, int n, int G,
    float* __restrict__ outh, float* __restrict__ outg) {
    int g = blockIdx.x;
    int lo = 0, hi = n;
    while (lo < hi) {
        int mid = (lo + hi) >> 1;
        if (batch[mid] < g) lo = mid + 1; else hi = mid;
    }
    int start = lo;
    hi = n;
    while (lo < hi) {
        int mid = (lo + hi) >> 1;
        if (batch[mid] < g + 1) lo = mid + 1; else hi = mid;
    }
    int end = lo;

    int tid = threadIdx.x;
    int c = tid & 63, gq = tid >> 6;
    float sc = g_scale[64 + c], sh = g_shift[64 + c];
    float s = 0.f, m = __int_as_float(NEG_INF_BITS);
    for (int r = start + gq; r < end; r += 4) {
        float v = __int_as_float(g_raw2[r * 64 + c]) * sc + sh;
        outh[(size_t)r * 64 + c] = v;
        s += v;
        m = fmaxf(m, v);
    }
    __shared__ float shs[256], shm[256];
    shs[tid] = s;
    shm[tid] = m;
    __syncthreads();
    if (gq == 0) {
#pragma unroll
        for (int q = 1; q < 4; q++) {
            s += shs[q * 64 + c];
            m = fmaxf(m, shm[q * 64 + c]);
        }
        int cnt = end - start;
        float mean = s / fmaxf((float)cnt, 1.f);
        float mx = (cnt > 0) ? m : __int_as_float(NEG_INF_BITS);
        outg[g * 128 + c] = mean;
        outg[g * 128 + 64 + c] = mx;
    }
}

// ------------------------------- launch ------------------------------------

extern "C" void kernel_launch(void* const* d_in, const int* in_sizes, int n_in,
                              void* d_out, int out_size) {
    const float* x    = (const float*)d_in[0];
    const int*   ei   = (const int*)d_in[1];
    const int*   batch = (const int*)d_in[2];
    const float* W1a = (const float*)d_in[3];
    const float* b1a = (const float*)d_in[4];
    const float* W1b = (const float*)d_in[5];
    const float* b1b = (const float*)d_in[6];
    const float* g1  = (const float*)d_in[7];
    const float* be1 = (const float*)d_in[8];
    const float* W2a = (const float*)d_in[9];
    const float* b2a = (const float*)d_in[10];
    const float* W2b = (const float*)d_in[11];
    const float* b2b = (const float*)d_in[12];
    const float* g2  = (const float*)d_in[13];
    const float* be2 = (const float*)d_in[14];

    int N = in_sizes[0] / 64;
    int E = in_sizes[1] / 2;
    int G = (out_size - N * 64) / 128;
    const int* src = ei;
    const int* dst = ei + E;

    float* outh = (float*)d_out;
    float* outg = outh + (size_t)N * 64;

    cudaFuncSetAttribute(k_edge_mma,
                         cudaFuncAttributeMaxDynamicSharedMemorySize,
                         SM_EDGE_TOTAL);

    int ntiles = (E + TILE_E - 1) / TILE_E;
    int egrid = 304;    // 2 CTAs/SM

    // [0] init raw1 + zero counters
    k_init_raw<<<2048, 256>>>(0, N * 64, N);
    // [1] node linear for layer 1
    k_nodelin<<<(N + 31) / 32, 256>>>(x, 0, W1a, b1a, N);
    // [2] histogram (independent of probe)
    k_hist<<<1024, 256>>>(dst, E);
    // [3] ncu probe: 304 CTAs x 1 tile over RAW edges (subset-max, neutral)
    k_edge_mma<<<304, 512, SM_EDGE_TOTAL>>>(W1b, b1b, src, dst, 1, 0, 304, E, 0);

    // --- rest of the counting sort ---
    int nch = (N + 1023) / 1024;
    k_scan1<<<nch, 1024>>>(N);
    k_scan2<<<1, 64>>>(nch);
    k_scan3<<<(N + 255) / 256, 256>>>(N);
    k_scatter<<<1024, 256>>>(src, dst, E);

    // --- layer 1 (full pass over sorted edges) ---
    k_edge_mma<<<egrid, 512, SM_EDGE_TOTAL>>>(W1b, b1b, src, dst, 0, 0, ntiles,
                                              E, 0);
    k_bnstats<<<128, 256>>>(0, N);
    k_bnfinal<<<1, 64>>>(g1, be1, N, 0);

    // --- layer 2 (BN1 folded into the node linear via g_scale/g_shift) ---
    k_nodelin<<<(N + 31) / 32, 256>>>(nullptr, 1, W2a, b2a, N);
    k_init_raw<<<2048, 256>>>(1, N * 64, 0);
    k_edge_mma<<<egrid, 512, SM_EDGE_TOTAL>>>(W2b, b2b, src, dst, 0, 0, ntiles,
                                              E, 1);
    k_bnstats<<<128, 256>>>(1, N);
    k_bnfinal<<<1, 64>>>(g2, be2, N, 1);

    // --- BN2 finalize + h write + mean/max pooling ---
    k_pool<<<G, 256>>>(batch, N, G, outh, outg);
}

// round 16
// speedup vs baseline: 1.3957x; 1.0282x over previous
#include <cuda_runtime.h>
#include <cuda_fp16.h>
#include <cstdint>

// ---------------------------------------------------------------------------
// GNNEncoder: 2x (EdgeConv -> BatchNorm) + mean/max pooling
//
// Algebra: concat[x_i, x_j-x_i] @ Wa = x_i@(Wtop-Wbot) + x_j@Wbot
//   => per-node A[i], B[j]; per-edge layer-1 is A[dst]+B[src]
// BatchNorm folded into next node GEMM / pooling. Edges counting-sorted by
// dst => run-dedup atomicMax epilogue.
// R16: probe dropped (diagnostics complete); k_nodelin processes 128 rows
//      per CTA (4 sub-blocks reuse the SMEM-resident W) => 4x fewer CTAs,
//      W L2 traffic 51MB -> 12.8MB. Edge kernel unchanged from R15.
// ---------------------------------------------------------------------------

#define HC 64
#define NMAX 50000
#define EMAX 1600000
#define NEG_INF_BITS ((int)0xFF800000u)

typedef unsigned long long u64;

#define FMA2(d, a, b, c) \
    asm("fma.rn.f32x2 %0, %1, %2, %3;" : "=l"(d) : "l"(a), "l"(b), "l"(c))
#define PACK2(d, v) \
    asm("mov.b64 %0, {%1, %1};" : "=l"(d) : "r"(v))
#define UNPACK2(lo, hi, v) \
    asm("mov.b64 {%0, %1}, %2;" : "=r"(lo), "=r"(hi) : "l"(v))

// fp32-accumulator f16 HMMA
#define MMAF16(c, a0, a1, a2, a3, b0, b1)                                    \
    asm volatile(                                                            \
        "mma.sync.aligned.m16n8k16.row.col.f32.f16.f16.f32 "                 \
        "{%0,%1,%2,%3}, {%4,%5,%6,%7}, {%8,%9}, {%0,%1,%2,%3};"              \
        : "+f"((c)[0]), "+f"((c)[1]), "+f"((c)[2]), "+f"((c)[3])             \
        : "r"(a0), "r"(a1), "r"(a2), "r"(a3), "r"(b0), "r"(b1))

__device__ __forceinline__ uint32_t pack_h2(__half lo, __half hi) {
    return (uint32_t)__half_as_ushort(lo) |
           ((uint32_t)__half_as_ushort(hi) << 16);
}
__device__ __forceinline__ uint32_t hpack(float x0, float x1) {
    return pack_h2(__float2half_rn(x0), __float2half_rn(x1));
}

__device__ int   g_cnt[NMAX];
__device__ int   g_chunk[256];
__device__ int2  g_edge[EMAX];        // (src, dst) sorted by dst
__device__ float g_A[NMAX * HC];
__device__ float g_B[NMAX * HC];
__device__ int   g_raw1[NMAX * HC];   // float bits, atomicMax as signed int
__device__ int   g_raw2[NMAX * HC];
__device__ float g_part[128 * 2 * HC];
__device__ float g_scale[2 * HC];
__device__ float g_shift[2 * HC];

// ---------------------------- small utilities ------------------------------

__global__ void k_init_raw(int layer, int n, int ncnt) {
    int* raw = layer ? g_raw2 : g_raw1;
    for (int i = blockIdx.x * blockDim.x + threadIdx.x; i < n;
         i += gridDim.x * blockDim.x) {
        raw[i] = NEG_INF_BITS;
        if (i < ncnt) g_cnt[i] = 0;
    }
}

__global__ void k_hist(const int* __restrict__ dst, int E) {
    for (int e = blockIdx.x * blockDim.x + threadIdx.x; e < E;
         e += gridDim.x * blockDim.x)
        atomicAdd(&g_cnt[dst[e]], 1);
}

__global__ void k_scan1(int n) {  // blockDim = 1024
    __shared__ int s[1024];
    int i = blockIdx.x * 1024 + threadIdx.x;
    int v = (i < n) ? g_cnt[i] : 0;
    s[threadIdx.x] = v;
    __syncthreads();
    for (int off = 1; off < 1024; off <<= 1) {
        int t = 0;
        if (threadIdx.x >= off) t = s[threadIdx.x - off];
        __syncthreads();
        s[threadIdx.x] += t;
        __syncthreads();
    }
    if (i < n) g_cnt[i] = s[threadIdx.x] - v;   // exclusive within chunk
    if (threadIdx.x == 1023) g_chunk[blockIdx.x] = s[1023];
}

__global__ void k_scan2(int nch) {  // blockDim = 64, nch <= 64
    __shared__ int s[64];
    int i = threadIdx.x;
    int v = (i < nch) ? g_chunk[i] : 0;
    s[i] = v;
    __syncthreads();
    for (int off = 1; off < 64; off <<= 1) {
        int t = (i >= off) ? s[i - off] : 0;
        __syncthreads();
        s[i] += t;
        __syncthreads();
    }
    if (i < nch) g_chunk[i] = s[i] - v;   // exclusive
}

__global__ void k_scan3(int n) {
    int i = blockIdx.x * blockDim.x + threadIdx.x;
    if (i < n) g_cnt[i] += g_chunk[i >> 10];
}

__global__ void k_scatter(const int* __restrict__ src,
                          const int* __restrict__ dst, int E) {
    for (int e = blockIdx.x * blockDim.x + threadIdx.x; e < E;
         e += gridDim.x * blockDim.x) {
        int d = dst[e];
        int p = atomicAdd(&g_cnt[d], 1);
        g_edge[p] = make_int2(src[e], d);
    }
}

// ------------------------- per-node linear (A, B) ---------------------------
// 128 rows per CTA in 4 sub-blocks of 32, reusing the SMEM-resident W.

__global__ __launch_bounds__(256) void k_nodelin(
    const float* __restrict__ xin, int use_raw,
    const float* __restrict__ Wa,  // [128,64] row-major
    const float* __restrict__ ba, int n) {
    __shared__ float Ws[128 * 64];
    __shared__ float xs[32 * 65];
    int tid = threadIdx.x;
    for (int i = tid; i < 128 * 64; i += 256) Ws[i] = Wa[i];

    int r = tid & 31, cg = tid >> 5;
    int c0 = cg * 8;

    for (int sb = 0; sb < 4; sb++) {
        int row0 = blockIdx.x * 128 + sb * 32;
        __syncthreads();
        for (int i = tid; i < 32 * 64; i += 256) {
            int rr = i >> 6, k = i & 63;
            int row = row0 + rr;
            float v = 0.f;
            if (row < n) {
                if (use_raw)
                    v = __int_as_float(g_raw1[row * 64 + k]) * g_scale[k] +
                        g_shift[k];
                else
                    v = xin[row * 64 + k];
            }
            xs[rr * 65 + k] = v;
        }
        __syncthreads();

        u64 a2[4], b2[4];
#pragma unroll
        for (int j = 0; j < 4; j++) { a2[j] = 0ull; b2[j] = 0ull; }

#pragma unroll 8
        for (int k = 0; k < 64; k++) {
            float xv = xs[r * 65 + k];
            u64 xp;
            PACK2(xp, __float_as_uint(xv));
            ulonglong2 t0 = *(const ulonglong2*)&Ws[k * 64 + c0];
            ulonglong2 t1 = *(const ulonglong2*)&Ws[k * 64 + c0 + 4];
            ulonglong2 q0 = *(const ulonglong2*)&Ws[(64 + k) * 64 + c0];
            ulonglong2 q1 = *(const ulonglong2*)&Ws[(64 + k) * 64 + c0 + 4];
            FMA2(a2[0], xp, t0.x, a2[0]);
            FMA2(a2[1], xp, t0.y, a2[1]);
            FMA2(a2[2], xp, t1.x, a2[2]);
            FMA2(a2[3], xp, t1.y, a2[3]);
            FMA2(b2[0], xp, q0.x, b2[0]);
            FMA2(b2[1], xp, q0.y, b2[1]);
            FMA2(b2[2], xp, q1.x, b2[2]);
            FMA2(b2[3], xp, q1.y, b2[3]);
        }
        int row = row0 + r;
        if (row < n) {
            float a[8], b[8];
#pragma unroll
            for (int j = 0; j < 4; j++) {
                unsigned int lo, hi;
                UNPACK2(lo, hi, a2[j]);
                a[2 * j] = __uint_as_float(lo);
                a[2 * j + 1] = __uint_as_float(hi);
                UNPACK2(lo, hi, b2[j]);
                b[2 * j] = __uint_as_float(lo);
                b[2 * j + 1] = __uint_as_float(hi);
            }
#pragma unroll
            for (int j = 0; j < 8; j++) {
                float bb = ba[c0 + j];
                g_A[row * 64 + c0 + j] = a[j] - b[j] + bb;
                g_B[row * 64 + c0 + j] = b[j];
            }
        }
    }
}

// --------- edge kernel (f16 2-term, W split exact, occupancy 2) -------------
// k-order permuted identically in A and W tiles (dot products invariant):
// orig k-pair word w stored at pos = (w&3)*8 + (w>>2); MMA thread fragments
// contiguous (LDS.64). 16 warps: warp (eg 0..7, nh 0..1) = 16 edges x 32 cols.

#define TILE_E 128
#define AROW 34                             // u32 stride per edge row (pad)
// dynamic smem (bytes)
#define SMO_DS   0                          // int [128]
#define SMO_SS   512                        // int [128]
#define SMO_AH   1024                       // [128][34] u32 = 17408 B
#define SMO_STG  18432                      // [64][132] f32 = 33792 B
#define SMO_WTH  18432                      // init-only alias, [64][34] u32
#define SMO_WTL  27136                      // init-only alias
#define SM_EDGE_TOTAL 52224

__global__ __launch_bounds__(512, 2) void k_edge_mma(
    const float* __restrict__ Wb,   // [64k][64n]
    const float* __restrict__ bb,   // [64]
    int tile_begin, int tile_end, int E, int layer) {
    extern __shared__ char sm[];
    int* ds = (int*)(sm + SMO_DS);
    int* ss = (int*)(sm + SMO_SS);
    uint32_t* AH = (uint32_t*)(sm + SMO_AH);
    float* STG = (float*)(sm + SMO_STG);
    uint32_t* WTH = (uint32_t*)(sm + SMO_WTH);
    uint32_t* WTL = (uint32_t*)(sm + SMO_WTL);

    int* out = layer ? g_raw2 : g_raw1;
    int tid = threadIdx.x;
    int wid = tid >> 5, lid = tid & 31;
    int gid = lid >> 2, tig = lid & 3;
    int eg = wid & 7, nh = wid >> 3;

    // ---- W exact split -> SMEM in permuted-k fragment layout ----
    for (int i = tid; i < 64 * 32; i += 512) {
        int n = i >> 5, wp = i & 31;           // orig k-pair index wp
        float w0 = Wb[(2 * wp) * 64 + n];
        float w1 = Wb[(2 * wp + 1) * 64 + n];
        __half h0 = __float2half_rn(w0);
        __half h1 = __float2half_rn(w1);
        __half l0 = __float2half_rn(w0 - __half2float(h0));
        __half l1 = __float2half_rn(w1 - __half2float(h1));
        int pos = (wp & 3) * 8 + (wp >> 2);
        WTH[n * AROW + pos] = pack_h2(h0, h1);
        WTL[n * AROW + pos] = pack_h2(l0, l1);
    }
    __syncthreads();

    // ---- W fragments to registers (held for whole kernel) ----
    uint32_t wh0[4][4], wh1[4][4], wl0[4][4], wl1[4][4];
#pragma unroll
    for (int kt = 0; kt < 4; kt++)
#pragma unroll
        for (int nt = 0; nt < 4; nt++) {
            int n = nh * 32 + nt * 8 + gid;
            uint2 wh = *(const uint2*)&WTH[n * AROW + tig * 8 + kt * 2];
            uint2 wl = *(const uint2*)&WTL[n * AROW + tig * 8 + kt * 2];
            wh0[kt][nt] = wh.x;
            wh1[kt][nt] = wh.y;
            wl0[kt][nt] = wl.x;
            wl1[kt][nt] = wl.y;
        }
    float bias[4][2];
#pragma unroll
    for (int nt = 0; nt < 4; nt++) {
        int c0 = nh * 32 + nt * 8 + tig * 2;
        bias[nt][0] = bb[c0];
        bias[nt][1] = bb[c0 + 1];
    }
    __syncthreads();   // done with WTH/WTL region (aliases staging)

    int stride = gridDim.x;
    int ge = tid >> 2, gp = tid & 3;   // gather: 4 threads/edge, 16 k each

    for (int t = tile_begin + (int)blockIdx.x; t < tile_end; t += stride) {
        // ---- 0. tile indices ----
        if (tid < TILE_E) {
            long long e = (long long)t * TILE_E + tid;
            if (e < E) {
                int2 v = g_edge[e];
                ds[tid] = v.y;
                ss[tid] = v.x;
            } else {
                ds[tid] = -1;
                ss[tid] = 0;
            }
        }
        __syncthreads();

        // ---- 1. gather + relu + f16 round -> AH (permuted-k layout) ----
        {
            int d = ds[ge], s = ss[ge];
            uint32_t hw[8];
            if (d >= 0) {
                const float4* ap =
                    (const float4*)&g_A[(size_t)d * 64 + gp * 16];
                const float4* bp =
                    (const float4*)&g_B[(size_t)s * 64 + gp * 16];
#pragma unroll
                for (int q = 0; q < 4; q++) {
                    float4 av = ap[q], bv = bp[q];
                    hw[2 * q] = hpack(fmaxf(av.x + bv.x, 0.f),
                                      fmaxf(av.y + bv.y, 0.f));
                    hw[2 * q + 1] = hpack(fmaxf(av.z + bv.z, 0.f),
                                          fmaxf(av.w + bv.w, 0.f));
                }
            } else {
#pragma unroll
                for (int j = 0; j < 8; j++) hw[j] = 0u;
            }
            uint32_t* ah = AH + ge * AROW + gp * 2;
#pragma unroll
            for (int jj = 0; jj < 4; jj++)
                *(uint2*)(ah + jj * 8) = make_uint2(hw[jj], hw[jj + 4]);
        }
        __syncthreads();

        // ---- 2. MMA: 2 terms (a*Wh + a*Wl), fp32 accum ----
        float acc[4][4];
#pragma unroll
        for (int nt = 0; nt < 4; nt++)
#pragma unroll
            for (int j = 0; j < 4; j++) acc[nt][j] = 0.f;

        int erow = eg * 16 + gid;
#pragma unroll
        for (int kt = 0; kt < 4; kt++) {
            int fo = tig * 8 + kt * 2;
            uint2 a02 = *(const uint2*)&AH[erow * AROW + fo];
            uint2 a13 = *(const uint2*)&AH[(erow + 8) * AROW + fo];
#pragma unroll
            for (int nt = 0; nt < 4; nt++) {
                MMAF16(acc[nt], a02.x, a13.x, a02.y, a13.y,
                       wh0[kt][nt], wh1[kt][nt]);
                MMAF16(acc[nt], a02.x, a13.x, a02.y, a13.y,
                       wl0[kt][nt], wl1[kt][nt]);
            }
        }

        // ---- 3. bias + relu -> staging [col][edge] stride 132 ----
#pragma unroll
        for (int nt = 0; nt < 4; nt++) {
            int c0 = nh * 32 + nt * 8 + tig * 2;
            STG[c0 * 132 + erow] = fmaxf(acc[nt][0] + bias[nt][0], 0.f);
            STG[(c0 + 1) * 132 + erow] = fmaxf(acc[nt][1] + bias[nt][1], 0.f);
            STG[c0 * 132 + erow + 8] = fmaxf(acc[nt][2] + bias[nt][0], 0.f);
            STG[(c0 + 1) * 132 + erow + 8] = fmaxf(acc[nt][3] + bias[nt][1], 0.f);
        }
        __syncthreads();   // STG ready

        // ---- 4. run-dedup atomicMax (edges sorted by dst) ----
        {
            int c = tid >> 3;
            int seg = (tid & 7) * 16;
            const float* sp = STG + c * 132 + seg;
            const int* dsc = ds + seg;
            float v[16];
#pragma unroll
            for (int q = 0; q < 4; q++) {
                float4 f = *(const float4*)(sp + q * 4);
                v[q * 4 + 0] = f.x; v[q * 4 + 1] = f.y;
                v[q * 4 + 2] = f.z; v[q * 4 + 3] = f.w;
            }
            int d = dsc[0];
            float m = v[0];
#pragma unroll
            for (int i = 1; i < 16; i++) {
                int dn = dsc[i];
                if (dn == d) {
                    m = fmaxf(m, v[i]);
                } else {
                    if (d >= 0) atomicMax(&out[d * 64 + c], __float_as_int(m));
                    d = dn;
                    m = v[i];
                }
            }
            if (d >= 0) atomicMax(&out[d * 64 + c], __float_as_int(m));
        }
        __syncthreads();   // ds/ss + AH + STG free for next tile
    }
}

// ------------------------------ batchnorm ----------------------------------

__global__ void k_bnstats(int layer, int n) {  // grid 128, block 256
    const int* raw = layer ? g_raw2 : g_raw1;
    int tid = threadIdx.x;
    int c = tid & 63, gq = tid >> 6;
    float s = 0.f, s2 = 0.f;
    for (int r = blockIdx.x * 4 + gq; r < n; r += 512) {
        float v = __int_as_float(raw[r * 64 + c]);
        s += v;
        s2 += v * v;
    }
    __shared__ float sh[256], sh2[256];
    sh[tid] = s;
    sh2[tid] = s2;
    __syncthreads();
    if (gq == 0) {
#pragma unroll
        for (int q = 1; q < 4; q++) {
            s += sh[q * 64 + c];
            s2 += sh2[q * 64 + c];
        }
        g_part[blockIdx.x * 128 + c] = s;
        g_part[blockIdx.x * 128 + 64 + c] = s2;
    }
}

__global__ void k_bnfinal(const float* __restrict__ gamma,
                          const float* __restrict__ beta, int n, int layer) {
    int c = threadIdx.x;
    if (c < 64) {
        float s = 0.f, s2 = 0.f;
        for (int b = 0; b < 128; b++) {
            s += g_part[b * 128 + c];
            s2 += g_part[b * 128 + 64 + c];
        }
        float mean = s / (float)n;
        float var = s2 / (float)n - mean * mean;
        float sc = gamma[c] * rsqrtf(var + 1e-5f);
        g_scale[layer * 64 + c] = sc;
        g_shift[layer * 64 + c] = beta[c] - mean * sc;
    }
}

// ---------------------- pooling + BN2 finalize + h write --------------------

__global__ __launch_bounds__(256) void k_pool(
    const int* __restrict__ batch, int n, int G,
    float* __restrict__ outh, float* __restrict__ outg) {
    int g = blockIdx.x;
    int lo = 0, hi = n;
    while (lo < hi) {
        int mid = (lo + hi) >> 1;
        if (batch[mid] < g) lo = mid + 1; else hi = mid;
    }
    int start = lo;
    hi = n;
    while (lo < hi) {
        int mid = (lo + hi) >> 1;
        if (batch[mid] < g + 1) lo = mid + 1; else hi = mid;
    }
    int end = lo;

    int tid = threadIdx.x;
    int c = tid & 63, gq = tid >> 6;
    float sc = g_scale[64 + c], sh = g_shift[64 + c];
    float s = 0.f, m = __int_as_float(NEG_INF_BITS);
    for (int r = start + gq; r < end; r += 4) {
        float v = __int_as_float(g_raw2[r * 64 + c]) * sc + sh;
        outh[(size_t)r * 64 + c] = v;
        s += v;
        m = fmaxf(m, v);
    }
    __shared__ float shs[256], shm[256];
    shs[tid] = s;
    shm[tid] = m;
    __syncthreads();
    if (gq == 0) {
#pragma unroll
        for (int q = 1; q < 4; q++) {
            s += shs[q * 64 + c];
            m = fmaxf(m, shm[q * 64 + c]);
        }
        int cnt = end - start;
        float mean = s / fmaxf((float)cnt, 1.f);
        float mx = (cnt > 0) ? m : __int_as_float(NEG_INF_BITS);
        outg[g * 128 + c] = mean;
        outg[g * 128 + 64 + c] = mx;
    }
}

// ------------------------------- launch ------------------------------------

extern "C" void kernel_launch(void* const* d_in, const int* in_sizes, int n_in,
                              void* d_out, int out_size) {
    const float* x    = (const float*)d_in[0];
    const int*   ei   = (const int*)d_in[1];
    const int*   batch = (const int*)d_in[2];
    const float* W1a = (const float*)d_in[3];
    const float* b1a = (const float*)d_in[4];
    const float* W1b = (const float*)d_in[5];
    const float* b1b = (const float*)d_in[6];
    const float* g1  = (const float*)d_in[7];
    const float* be1 = (const float*)d_in[8];
    const float* W2a = (const float*)d_in[9];
    const float* b2a = (const float*)d_in[10];
    const float* W2b = (const float*)d_in[11];
    const float* b2b = (const float*)d_in[12];
    const float* g2  = (const float*)d_in[13];
    const float* be2 = (const float*)d_in[14];

    int N = in_sizes[0] / 64;
    int E = in_sizes[1] / 2;
    int G = (out_size - N * 64) / 128;
    const int* src = ei;
    const int* dst = ei + E;

    float* outh = (float*)d_out;
    float* outg = outh + (size_t)N * 64;

    cudaFuncSetAttribute(k_edge_mma,
                         cudaFuncAttributeMaxDynamicSharedMemorySize,
                         SM_EDGE_TOTAL);

    int ntiles = (E + TILE_E - 1) / TILE_E;
    int egrid = 304;    // 2 CTAs/SM
    int ngrid = (N + 127) / 128;

    // init raw1 + zero counters
    k_init_raw<<<2048, 256>>>(0, N * 64, N);
    // node linear for layer 1
    k_nodelin<<<ngrid, 256>>>(x, 0, W1a, b1a, N);

    // --- counting sort of edges by dst ---
    k_hist<<<1024, 256>>>(dst, E);
    int nch = (N + 1023) / 1024;
    k_scan1<<<nch, 1024>>>(N);
    k_scan2<<<1, 64>>>(nch);
    k_scan3<<<(N + 255) / 256, 256>>>(N);
    k_scatter<<<1024, 256>>>(src, dst, E);

    // --- layer 1 (full pass over sorted edges) ---
    k_edge_mma<<<egrid, 512, SM_EDGE_TOTAL>>>(W1b, b1b, 0, ntiles, E, 0);
    k_bnstats<<<128, 256>>>(0, N);
    k_bnfinal<<<1, 64>>>(g1, be1, N, 0);

    // --- layer 2 (BN1 folded into the node linear via g_scale/g_shift) ---
    k_nodelin<<<ngrid, 256>>>(nullptr, 1, W2a, b2a, N);
    k_init_raw<<<2048, 256>>>(1, N * 64, 0);
    k_edge_mma<<<egrid, 512, SM_EDGE_TOTAL>>>(W2b, b2b, 0, ntiles, E, 1);
    k_bnstats<<<128, 256>>>(1, N);
    k_bnfinal<<<1, 64>>>(g2, be2, N, 1);

    // --- BN2 finalize + h write + mean/max pooling ---
    k_pool<<<G, 256>>>(batch, N, G, outh, outg);
}